// round 10
// baseline (speedup 1.0000x reference)
#include <cuda_runtime.h>
#include <cuda_bf16.h>
#include <cuda_fp16.h>
#include <stdint.h>

#define B_ 8
#define T_ 2048
#define D_ 1024
#define SCALE_ 0.03125f   // 1/sqrt(1024)

// k_qk config (unchanged, passing)
#define NSTAGE 3
#define A_BYTES 8192
#define B_BYTES 16384
#define STAGE_BYTES (A_BYTES + B_BYTES)   // 24576

// k_av config: CTA 128x128, 4 warps of 64x64, 3-stage
#define AV_NSTAGE 3
#define AV_STAGE 32768      // A 128x128B + B 128x128B

// ---------------------------------------------------------------------------
// Scratch
// ---------------------------------------------------------------------------
__device__ __nv_bfloat16 g_Xh [(size_t)B_ * T_ * D_];   // x bf16 (QK operands)
__device__ __half        g_XhT[(size_t)B_ * D_ * T_];   // x^T f16 (AV B operand)
__device__ __half        g_Sh [(size_t)B_ * T_ * T_];   // exp(masked logits), f16
__device__ __half        g_Ch [(size_t)B_ * T_ * D_];   // context f16
__device__ float         g_den[B_ * T_];                // softmax denominators

// ---------------------------------------------------------------------------
// Helpers
// ---------------------------------------------------------------------------
__device__ __forceinline__ uint32_t smem_u32(const void* p) {
    uint32_t a;
    asm("{ .reg .u64 t; cvta.to.shared.u64 t, %1; cvt.u32.u64 %0, t; }"
        : "=r"(a) : "l"(p));
    return a;
}

__device__ __forceinline__ void cp16(uint32_t dst, const void* src) {
    asm volatile("cp.async.cg.shared.global [%0], [%1], 16;"
                 :: "r"(dst), "l"(src) : "memory");
}
#define CP_COMMIT() asm volatile("cp.async.commit_group;" ::: "memory")
#define CP_WAIT(N)  asm volatile("cp.async.wait_group %0;" :: "n"(N) : "memory")

__device__ __forceinline__ void ldmx4(uint32_t& r0, uint32_t& r1,
                                      uint32_t& r2, uint32_t& r3, uint32_t addr) {
    asm volatile("ldmatrix.sync.aligned.m8n8.x4.shared.b16 {%0,%1,%2,%3}, [%4];"
                 : "=r"(r0), "=r"(r1), "=r"(r2), "=r"(r3) : "r"(addr));
}

__device__ __forceinline__ void mma_bf16(float* c, const uint32_t* a,
                                         uint32_t b0, uint32_t b1) {
    asm volatile(
        "mma.sync.aligned.m16n8k16.row.col.f32.bf16.bf16.f32 "
        "{%0,%1,%2,%3}, {%4,%5,%6,%7}, {%8,%9}, {%0,%1,%2,%3};"
        : "+f"(c[0]), "+f"(c[1]), "+f"(c[2]), "+f"(c[3])
        : "r"(a[0]), "r"(a[1]), "r"(a[2]), "r"(a[3]), "r"(b0), "r"(b1));
}

__device__ __forceinline__ void mma_f16(float* c, const uint32_t* a,
                                        uint32_t b0, uint32_t b1) {
    asm volatile(
        "mma.sync.aligned.m16n8k16.row.col.f32.f16.f16.f32 "
        "{%0,%1,%2,%3}, {%4,%5,%6,%7}, {%8,%9}, {%0,%1,%2,%3};"
        : "+f"(c[0]), "+f"(c[1]), "+f"(c[2]), "+f"(c[3])
        : "r"(a[0]), "r"(a[1]), "r"(a[2]), "r"(a[3]), "r"(b0), "r"(b1));
}

__device__ __forceinline__ uint32_t sw128(uint32_t off) {
    return off ^ ((off >> 3) & 0x70);
}

__device__ __forceinline__ float softplusf_(float v) {
    return v > 20.f ? v : log1pf(__expf(v));
}
__device__ __forceinline__ float gelu_tanh_(float v) {
    float u = 0.7978845608028654f * (v + 0.044715f * v * v * v);
    return 0.5f * v * (1.f + tanhf(u));
}

// ---------------------------------------------------------------------------
// Kernel Z: zero denominators
// ---------------------------------------------------------------------------
__global__ void k_zero() {
    const int i = blockIdx.x * 1024 + threadIdx.x;
    if (i < B_ * T_) g_den[i] = 0.f;
}

// ---------------------------------------------------------------------------
// Kernel 0: convert x -> bf16 row-major + f16 transposed
// ---------------------------------------------------------------------------
__global__ __launch_bounds__(256) void k_cvt(const float* __restrict__ x) {
    __shared__ float tile[32][33];
    const int b  = blockIdx.z;
    const int t0 = blockIdx.x * 32;
    const int d0 = blockIdx.y * 32;
    const int lx = threadIdx.x;
    const int ly = threadIdx.y;
    const float* X = x + (size_t)b * T_ * D_;

#pragma unroll
    for (int r = 0; r < 2; r++) {
        const int t = t0 + ly + r * 16;
        const int d = d0 + lx * 2;
        float2 v = *(const float2*)(X + (size_t)t * D_ + d);
        __nv_bfloat162 h = __floats2bfloat162_rn(v.x, v.y);
        *(uint32_t*)(g_Xh + (size_t)(b * T_ + t) * D_ + d) = *(uint32_t*)&h;
        tile[ly + r * 16][lx * 2 + 0] = v.x;
        tile[ly + r * 16][lx * 2 + 1] = v.y;
    }
    __syncthreads();
#pragma unroll
    for (int r = 0; r < 2; r++) {
        const int d  = d0 + ly + r * 16;
        const int tp = lx * 2;
        __half2 h = __floats2half2_rn(tile[tp + 0][ly + r * 16],
                                      tile[tp + 1][ly + r * 16]);
        *(uint32_t*)(g_XhT + ((size_t)b * D_ + d) * T_ + t0 + tp) = *(uint32_t*)&h;
    }
}

// ---------------------------------------------------------------------------
// k_qk MMA core (unchanged): CTA 64x128, 8 warps 2m x 4n of 32x32, bf16
// ---------------------------------------------------------------------------
__device__ __forceinline__ void mma_chunk_qk(uint32_t sA, uint32_t sB,
                                             int warp_m, int warp_n, int lane,
                                             float c[2][4][4]) {
    const int rowsel = lane & 15;
    const int khalf  = (lane >> 4) * 16;
    const uint32_t a0 = sA + (warp_m * 32 + 0  + rowsel) * 128;
    const uint32_t a1 = sA + (warp_m * 32 + 16 + rowsel) * 128;
    const uint32_t b0a = sB + (warp_n * 32 + 0  + rowsel) * 128;
    const uint32_t b1a = sB + (warp_n * 32 + 16 + rowsel) * 128;
    const uint32_t xa0 = ((warp_m * 32 + 0  + rowsel) & 7) << 4;
    const uint32_t xa1 = ((warp_m * 32 + 16 + rowsel) & 7) << 4;
    const uint32_t xb0 = ((warp_n * 32 + 0  + rowsel) & 7) << 4;
    const uint32_t xb1 = ((warp_n * 32 + 16 + rowsel) & 7) << 4;
#pragma unroll
    for (int ks = 0; ks < 4; ks++) {
        const uint32_t kb = ks * 32 + khalf;
        uint32_t a[2][4];
        ldmx4(a[0][0], a[0][1], a[0][2], a[0][3], a0 + (kb ^ xa0));
        ldmx4(a[1][0], a[1][1], a[1][2], a[1][3], a1 + (kb ^ xa1));
        uint32_t b[4][2];
        {
            uint32_t r0, r1, r2, r3;
            ldmx4(r0, r1, r2, r3, b0a + (kb ^ xb0));
            b[0][0] = r0; b[1][0] = r1; b[0][1] = r2; b[1][1] = r3;
            ldmx4(r0, r1, r2, r3, b1a + (kb ^ xb1));
            b[2][0] = r0; b[3][0] = r1; b[2][1] = r2; b[3][1] = r3;
        }
#pragma unroll
        for (int mi = 0; mi < 2; mi++)
#pragma unroll
            for (int ni = 0; ni < 4; ni++)
                mma_bf16(c[mi][ni], a[mi], b[ni][0], b[ni][1]);
    }
}

__device__ __forceinline__ void load_tileA64(uint32_t sdst, const void* srcv,
                                             size_t row_stride_elts, int tid) {
    const __nv_bfloat16* src = (const __nv_bfloat16*)srcv;
    const int row = tid >> 2;
    const int cb  = (tid & 3) * 2;
    const __nv_bfloat16* g = src + (size_t)row * row_stride_elts + cb * 8;
#pragma unroll
    for (int c = 0; c < 2; c++)
        cp16(sdst + sw128(row * 128 + (cb + c) * 16), g + c * 8);
}
// 128 rows x 128B with 256 threads
__device__ __forceinline__ void load_tileB128(uint32_t sdst, const void* srcv,
                                              size_t row_stride_elts, int tid) {
    const __half* src = (const __half*)srcv;
    const int row = tid >> 1;
    const int cb  = (tid & 1) * 4;
    const __half* g = src + (size_t)row * row_stride_elts + cb * 8;
#pragma unroll
    for (int c = 0; c < 4; c++)
        cp16(sdst + sw128(row * 128 + (cb + c) * 16), g + c * 8);
}
// 128 rows x 128B with 128 threads (one row per thread)
__device__ __forceinline__ void load_rows128(uint32_t sdst, const __half* src,
                                             size_t row_stride_elts, int tid) {
    const __half* g = src + (size_t)tid * row_stride_elts;
    const uint32_t ro = (uint32_t)tid * 128;
#pragma unroll
    for (int c = 0; c < 8; c++)
        cp16(sdst + sw128(ro + c * 16), g + c * 8);
}

// ---------------------------------------------------------------------------
// Kernel 1: S = exp(SCALE * X X^T) f16, strict causal, fused row-sum
// ---------------------------------------------------------------------------
__global__ __launch_bounds__(256, 3) void k_qk_mma() {
    const int sb  = blockIdx.x;
    const int tb6 = blockIdx.y;
    const int b   = blockIdx.z;
    if (sb > (tb6 >> 1)) return;

    extern __shared__ __align__(1024) char smem[];
    __shared__ float rsum[64];
    const uint32_t sbase = smem_u32(smem);
    const int tid = threadIdx.x, lane = tid & 31, wid = tid >> 5;
    const int warp_m = wid & 1, warp_n = wid >> 1;

    if (tid < 64) rsum[tid] = 0.f;

    const __nv_bfloat16* A0 = g_Xh + (size_t)(b * T_ + tb6 * 64)  * D_;
    const __nv_bfloat16* B0 = g_Xh + (size_t)(b * T_ + sb * 128)  * D_;

    float c[2][4][4];
#pragma unroll
    for (int mi = 0; mi < 2; mi++)
#pragma unroll
        for (int ni = 0; ni < 4; ni++)
#pragma unroll
            for (int k = 0; k < 4; k++) c[mi][ni][k] = 0.f;

    const int nIter = D_ / 64;
#pragma unroll
    for (int s = 0; s < NSTAGE - 1; s++) {
        const uint32_t st = sbase + s * STAGE_BYTES;
        load_tileA64(st,            A0 + s * 64, D_, tid);
        load_tileB128(st + A_BYTES, B0 + s * 64, D_, tid);
        CP_COMMIT();
    }

    for (int it = 0; it < nIter; ++it) {
        if (it + NSTAGE - 1 < nIter) CP_WAIT(NSTAGE - 2); else CP_WAIT(0);
        __syncthreads();
        if (it + NSTAGE - 1 < nIter) {
            const int ld = it + NSTAGE - 1;
            const uint32_t stb = sbase + (ld % NSTAGE) * STAGE_BYTES;
            load_tileA64(stb,            A0 + ld * 64, D_, tid);
            load_tileB128(stb + A_BYTES, B0 + ld * 64, D_, tid);
            CP_COMMIT();
        }
        const uint32_t st = sbase + (it % NSTAGE) * STAGE_BYTES;
        mma_chunk_qk(st, st + A_BYTES, warp_m, warp_n, lane, c);
    }

    const int quad = lane >> 2, qid = lane & 3;
    const float C2 = 0.045084219f;   // SCALE * log2(e)
#pragma unroll
    for (int mi = 0; mi < 2; mi++) {
        float rs[2] = {0.f, 0.f};
#pragma unroll
        for (int h = 0; h < 2; h++) {
            const int row = warp_m * 32 + mi * 16 + quad + h * 8;
            const int t   = tb6 * 64 + row;
#pragma unroll
            for (int ni = 0; ni < 4; ni++) {
                const int col = warp_n * 32 + ni * 8 + qid * 2;
                const int s0  = sb * 128 + col;
                const float z0 = (s0 + 0 < t) ? c[mi][ni][2 * h + 0] * C2 : -64.f;
                const float z1 = (s0 + 1 < t) ? c[mi][ni][2 * h + 1] * C2 : -64.f;
                __half2 e = h2exp2(__floats2half2_rn(z0, z1));
                *(uint32_t*)(g_Sh + ((size_t)(b * T_ + t)) * T_ + s0) = *(uint32_t*)&e;
                float2 ef = __half22float2(e);
                rs[h] += ef.x + ef.y;
            }
        }
#pragma unroll
        for (int h = 0; h < 2; h++) {
            float v = rs[h];
            v += __shfl_xor_sync(0xFFFFFFFFu, v, 1);
            v += __shfl_xor_sync(0xFFFFFFFFu, v, 2);
            if (qid == 0) {
                const int row = warp_m * 32 + mi * 16 + quad + h * 8;
                atomicAdd(&rsum[row], v);
            }
        }
    }
    __syncthreads();
    if (tid < 64)
        atomicAdd(&g_den[b * T_ + tb6 * 64 + tid], rsum[tid]);
}

// ---------------------------------------------------------------------------
// Kernel 3: context = (S @ X) / den. CTA 128x128, 4 warps of 64x64,
// 128 threads, 3-stage, 2 CTA/SM. f16 in, f16 out. Heavy tiles first.
// ---------------------------------------------------------------------------
__global__ __launch_bounds__(128, 2) void k_av_mma() {
    const int nb = blockIdx.x;
    const int tb = 15 - (int)blockIdx.y;   // heavy-first
    const int b  = blockIdx.z;

    extern __shared__ __align__(1024) char smem[];
    const uint32_t sbase = smem_u32(smem);
    const int tid = threadIdx.x, lane = tid & 31, wid = tid >> 5;
    const int warp_m = wid & 1, warp_n = wid >> 1;   // 2x2 of 64x64

    const __half* A0 = g_Sh  + (size_t)(b * T_ + tb * 128) * T_;
    const __half* B0 = g_XhT + ((size_t)b * D_ + nb * 128) * T_;

    float c[4][8][4];
#pragma unroll
    for (int mi = 0; mi < 4; mi++)
#pragma unroll
        for (int ni = 0; ni < 8; ni++)
#pragma unroll
            for (int k = 0; k < 4; k++) c[mi][ni][k] = 0.f;

    const int nIter = (tb + 1) * 2;
#pragma unroll
    for (int s = 0; s < AV_NSTAGE - 1; s++) {
        if (s < nIter) {
            const uint32_t st = sbase + s * AV_STAGE;
            load_rows128(st,         A0 + s * 64, T_, tid);
            load_rows128(st + 16384, B0 + s * 64, T_, tid);
            CP_COMMIT();
        }
    }

    const int rowsel = lane & 15;
    const int khalf  = (lane >> 4) * 16;

    for (int it = 0; it < nIter; ++it) {
        if (it + AV_NSTAGE - 1 < nIter) CP_WAIT(AV_NSTAGE - 2); else CP_WAIT(0);
        __syncthreads();
        if (it + AV_NSTAGE - 1 < nIter) {
            const int ld = it + AV_NSTAGE - 1;
            const uint32_t stb = sbase + (ld % AV_NSTAGE) * AV_STAGE;
            load_rows128(stb,         A0 + ld * 64, T_, tid);
            load_rows128(stb + 16384, B0 + ld * 64, T_, tid);
            CP_COMMIT();
        }
        const uint32_t sA = sbase + (it % AV_NSTAGE) * AV_STAGE;
        const uint32_t sB = sA + 16384;
#pragma unroll
        for (int ks = 0; ks < 4; ks++) {
            const uint32_t kb = ks * 32 + khalf;
            uint32_t a[4][4];
#pragma unroll
            for (int mi = 0; mi < 4; mi++) {
                const uint32_t row = warp_m * 64 + mi * 16 + rowsel;
                ldmx4(a[mi][0], a[mi][1], a[mi][2], a[mi][3],
                      sA + row * 128 + (kb ^ ((row & 7) << 4)));
            }
            uint32_t bf[8][2];
#pragma unroll
            for (int nj = 0; nj < 4; nj++) {
                const uint32_t nrow = warp_n * 64 + nj * 16 + rowsel;
                uint32_t r0, r1, r2, r3;
                ldmx4(r0, r1, r2, r3, sB + nrow * 128 + (kb ^ ((nrow & 7) << 4)));
                bf[nj * 2 + 0][0] = r0; bf[nj * 2 + 1][0] = r1;
                bf[nj * 2 + 0][1] = r2; bf[nj * 2 + 1][1] = r3;
            }
#pragma unroll
            for (int mi = 0; mi < 4; mi++)
#pragma unroll
                for (int ni = 0; ni < 8; ni++)
                    mma_f16(c[mi][ni], a[mi], bf[ni][0], bf[ni][1]);
        }
    }

    // epilogue: divide by denom, f16 store
    const int quad = lane >> 2, qid = lane & 3;
#pragma unroll
    for (int mi = 0; mi < 4; mi++) {
#pragma unroll
        for (int h = 0; h < 2; h++) {
            const int row = warp_m * 64 + mi * 16 + quad + h * 8;
            const int t   = tb * 128 + row;
            const float den = g_den[b * T_ + t];
            const float inv = den > 0.f ? 1.f / den : 0.f;
            __half* crow = g_Ch + ((size_t)(b * T_ + t)) * D_ + nb * 128;
#pragma unroll
            for (int ni = 0; ni < 8; ni++) {
                const int col = warp_n * 64 + ni * 8 + qid * 2;
                __half2 hv = __floats2half2_rn(c[mi][ni][2 * h + 0] * inv,
                                               c[mi][ni][2 * h + 1] * inv);
                *(uint32_t*)(crow + col) = *(uint32_t*)&hv;
            }
        }
    }
}

// ---------------------------------------------------------------------------
// Kernel 4: cosine / novelty / gate / tanh-GELU (C in f16)
// ---------------------------------------------------------------------------
__global__ __launch_bounds__(256) void k_epi(const float* __restrict__ x,
                                             const float* __restrict__ p_la,
                                             const float* __restrict__ p_ls,
                                             float* __restrict__ out) {
    const int row = blockIdx.x;
    const int tid = threadIdx.x;
    const float4 xv = *((const float4*)x + (size_t)row * 256 + tid);
    const uint2 cu  = *((const uint2*)g_Ch + (size_t)row * 256 + tid);
    float2 c01 = __half22float2(*(const __half2*)&cu.x);
    float2 c23 = __half22float2(*(const __half2*)&cu.y);

    float xx = xv.x * xv.x + xv.y * xv.y + xv.z * xv.z + xv.w * xv.w;
    float cc = c01.x * c01.x + c01.y * c01.y + c23.x * c23.x + c23.y * c23.y;
    float xc = xv.x * c01.x + xv.y * c01.y + xv.z * c23.x + xv.w * c23.y;

#pragma unroll
    for (int o = 16; o; o >>= 1) {
        xx += __shfl_down_sync(0xFFFFFFFFu, xx, o);
        cc += __shfl_down_sync(0xFFFFFFFFu, cc, o);
        xc += __shfl_down_sync(0xFFFFFFFFu, xc, o);
    }

    __shared__ float s_xx[8], s_cc[8], s_xc[8];
    __shared__ float s_gate;
    const int lane = tid & 31, w = tid >> 5;
    if (lane == 0) { s_xx[w] = xx; s_cc[w] = cc; s_xc[w] = xc; }
    __syncthreads();
    if (tid == 0) {
        float fxx = 0.f, fcc = 0.f, fxc = 0.f;
#pragma unroll
        for (int k = 0; k < 8; k++) { fxx += s_xx[k]; fcc += s_cc[k]; fxc += s_xc[k]; }
        const float nx = fmaxf(sqrtf(fxx), 1e-12f);
        const float nc = fmaxf(sqrtf(fcc), 1e-12f);
        const float cosv = fxc / (nx * nc);
        const float nov  = fminf(fmaxf(1.f - cosv, 0.f), 2.f) * 0.5f;
        const float alpha = softplusf_(*p_la);
        const float sigma = softplusf_(*p_ls);
        s_gate = 1.f + alpha * tanhf(sigma * nov);
    }
    __syncthreads();
    const float g = s_gate;

    float4 o;
    o.x = gelu_tanh_(xv.x * g);
    o.y = gelu_tanh_(xv.y * g);
    o.z = gelu_tanh_(xv.z * g);
    o.w = gelu_tanh_(xv.w * g);
    *((float4*)out + (size_t)row * 256 + tid) = o;
}

// ---------------------------------------------------------------------------
extern "C" void kernel_launch(void* const* d_in, const int* in_sizes, int n_in,
                              void* d_out, int out_size) {
    const float* x  = (const float*)d_in[0];
    const float* la = (const float*)d_in[1];
    const float* ls = (const float*)d_in[2];
    float* out = (float*)d_out;

    const int qk_smem = NSTAGE * STAGE_BYTES;      // 73728
    const int av_smem = AV_NSTAGE * AV_STAGE;      // 98304
    cudaFuncSetAttribute(k_qk_mma, cudaFuncAttributeMaxDynamicSharedMemorySize, qk_smem);
    cudaFuncSetAttribute(k_av_mma, cudaFuncAttributeMaxDynamicSharedMemorySize, av_smem);

    k_zero<<<(B_ * T_ + 1023) / 1024, 1024>>>();

    dim3 gc(T_ / 32, D_ / 32, B_);
    k_cvt<<<gc, dim3(16, 16)>>>(x);

    dim3 g1(16, 32, B_);
    k_qk_mma<<<g1, 256, qk_smem>>>();

    dim3 g3(8, 16, B_);
    k_av_mma<<<g3, 128, av_smem>>>();

    k_epi<<<B_ * T_, 256>>>(x, la, ls, out);
}

// round 12
// speedup vs baseline: 1.1724x; 1.1724x over previous
#include <cuda_runtime.h>
#include <cuda_bf16.h>
#include <cuda_fp16.h>
#include <stdint.h>

#define B_ 8
#define T_ 2048
#define D_ 1024
#define SCALE_ 0.03125f   // 1/sqrt(1024)

// k_qk config
#define NSTAGE 3
#define A_BYTES 8192
#define B_BYTES 16384
#define STAGE_BYTES (A_BYTES + B_BYTES)   // 24576

// k_av config (R4/R8 proven shape)
#define AV_NSTAGE 3
#define AV_STAGE 32768      // A 128x128B + B 128x128B

// ---------------------------------------------------------------------------
// Scratch
// ---------------------------------------------------------------------------
__device__ __nv_bfloat16 g_Xh [(size_t)B_ * T_ * D_];   // x bf16
__device__ __half        g_XhT[(size_t)B_ * D_ * T_];   // x^T f16
__device__ __half        g_Sh [(size_t)B_ * T_ * T_];   // exp(masked logits), f16
__device__ float         g_den[B_ * T_];                // softmax denominators
__device__ float         g_cc [B_ * T_];                // sum c*c per row
__device__ float         g_xc [B_ * T_];                // sum x*c per row

// ---------------------------------------------------------------------------
// Helpers
// ---------------------------------------------------------------------------
__device__ __forceinline__ uint32_t smem_u32(const void* p) {
    uint32_t a;
    asm("{ .reg .u64 t; cvta.to.shared.u64 t, %1; cvt.u32.u64 %0, t; }"
        : "=r"(a) : "l"(p));
    return a;
}

__device__ __forceinline__ void cp16(uint32_t dst, const void* src) {
    asm volatile("cp.async.cg.shared.global [%0], [%1], 16;"
                 :: "r"(dst), "l"(src) : "memory");
}
#define CP_COMMIT() asm volatile("cp.async.commit_group;" ::: "memory")
#define CP_WAIT(N)  asm volatile("cp.async.wait_group %0;" :: "n"(N) : "memory")

__device__ __forceinline__ void ldmx4(uint32_t& r0, uint32_t& r1,
                                      uint32_t& r2, uint32_t& r3, uint32_t addr) {
    asm volatile("ldmatrix.sync.aligned.m8n8.x4.shared.b16 {%0,%1,%2,%3}, [%4];"
                 : "=r"(r0), "=r"(r1), "=r"(r2), "=r"(r3) : "r"(addr));
}

__device__ __forceinline__ void mma_bf16(float* c, const uint32_t* a,
                                         uint32_t b0, uint32_t b1) {
    asm volatile(
        "mma.sync.aligned.m16n8k16.row.col.f32.bf16.bf16.f32 "
        "{%0,%1,%2,%3}, {%4,%5,%6,%7}, {%8,%9}, {%0,%1,%2,%3};"
        : "+f"(c[0]), "+f"(c[1]), "+f"(c[2]), "+f"(c[3])
        : "r"(a[0]), "r"(a[1]), "r"(a[2]), "r"(a[3]), "r"(b0), "r"(b1));
}

__device__ __forceinline__ void mma_f16(float* c, const uint32_t* a,
                                        uint32_t b0, uint32_t b1) {
    asm volatile(
        "mma.sync.aligned.m16n8k16.row.col.f32.f16.f16.f32 "
        "{%0,%1,%2,%3}, {%4,%5,%6,%7}, {%8,%9}, {%0,%1,%2,%3};"
        : "+f"(c[0]), "+f"(c[1]), "+f"(c[2]), "+f"(c[3])
        : "r"(a[0]), "r"(a[1]), "r"(a[2]), "r"(a[3]), "r"(b0), "r"(b1));
}

__device__ __forceinline__ uint32_t sw128(uint32_t off) {
    return off ^ ((off >> 3) & 0x70);
}

__device__ __forceinline__ float softplusf_(float v) {
    return v > 20.f ? v : log1pf(__expf(v));
}
__device__ __forceinline__ float gelu_tanh_(float v) {
    float u = 0.7978845608028654f * (v + 0.044715f * v * v * v);
    return 0.5f * v * (1.f + tanhf(u));
}

// ---------------------------------------------------------------------------
// Kernel Z: zero row accumulators
// ---------------------------------------------------------------------------
__global__ void k_zero() {
    const int i = blockIdx.x * 1024 + threadIdx.x;
    if (i < B_ * T_) { g_den[i] = 0.f; g_cc[i] = 0.f; g_xc[i] = 0.f; }
}

// ---------------------------------------------------------------------------
// Kernel 0: convert x -> bf16 row-major + f16 transposed
// ---------------------------------------------------------------------------
__global__ __launch_bounds__(256) void k_cvt(const float* __restrict__ x) {
    __shared__ float tile[32][33];
    const int b  = blockIdx.z;
    const int t0 = blockIdx.x * 32;
    const int d0 = blockIdx.y * 32;
    const int lx = threadIdx.x;
    const int ly = threadIdx.y;
    const float* X = x + (size_t)b * T_ * D_;

#pragma unroll
    for (int r = 0; r < 2; r++) {
        const int t = t0 + ly + r * 16;
        const int d = d0 + lx * 2;
        float2 v = *(const float2*)(X + (size_t)t * D_ + d);
        __nv_bfloat162 h = __floats2bfloat162_rn(v.x, v.y);
        *(uint32_t*)(g_Xh + (size_t)(b * T_ + t) * D_ + d) = *(uint32_t*)&h;
        tile[ly + r * 16][lx * 2 + 0] = v.x;
        tile[ly + r * 16][lx * 2 + 1] = v.y;
    }
    __syncthreads();
#pragma unroll
    for (int r = 0; r < 2; r++) {
        const int d  = d0 + ly + r * 16;
        const int tp = lx * 2;
        __half2 h = __floats2half2_rn(tile[tp + 0][ly + r * 16],
                                      tile[tp + 1][ly + r * 16]);
        *(uint32_t*)(g_XhT + ((size_t)b * D_ + d) * T_ + t0 + tp) = *(uint32_t*)&h;
    }
}

// ---------------------------------------------------------------------------
// k_qk MMA core: CTA 64x128, 8 warps 2m x 4n of 32x32, bf16
// ---------------------------------------------------------------------------
__device__ __forceinline__ void mma_chunk_qk(uint32_t sA, uint32_t sB,
                                             int warp_m, int warp_n, int lane,
                                             float c[2][4][4]) {
    const int rowsel = lane & 15;
    const int khalf  = (lane >> 4) * 16;
    const uint32_t a0 = sA + (warp_m * 32 + 0  + rowsel) * 128;
    const uint32_t a1 = sA + (warp_m * 32 + 16 + rowsel) * 128;
    const uint32_t b0a = sB + (warp_n * 32 + 0  + rowsel) * 128;
    const uint32_t b1a = sB + (warp_n * 32 + 16 + rowsel) * 128;
    const uint32_t xa0 = ((warp_m * 32 + 0  + rowsel) & 7) << 4;
    const uint32_t xa1 = ((warp_m * 32 + 16 + rowsel) & 7) << 4;
    const uint32_t xb0 = ((warp_n * 32 + 0  + rowsel) & 7) << 4;
    const uint32_t xb1 = ((warp_n * 32 + 16 + rowsel) & 7) << 4;
#pragma unroll
    for (int ks = 0; ks < 4; ks++) {
        const uint32_t kb = ks * 32 + khalf;
        uint32_t a[2][4];
        ldmx4(a[0][0], a[0][1], a[0][2], a[0][3], a0 + (kb ^ xa0));
        ldmx4(a[1][0], a[1][1], a[1][2], a[1][3], a1 + (kb ^ xa1));
        uint32_t b[4][2];
        {
            uint32_t r0, r1, r2, r3;
            ldmx4(r0, r1, r2, r3, b0a + (kb ^ xb0));
            b[0][0] = r0; b[1][0] = r1; b[0][1] = r2; b[1][1] = r3;
            ldmx4(r0, r1, r2, r3, b1a + (kb ^ xb1));
            b[2][0] = r0; b[3][0] = r1; b[2][1] = r2; b[3][1] = r3;
        }
#pragma unroll
        for (int mi = 0; mi < 2; mi++)
#pragma unroll
            for (int ni = 0; ni < 4; ni++)
                mma_bf16(c[mi][ni], a[mi], b[ni][0], b[ni][1]);
    }
}

__device__ __forceinline__ void load_tileA64(uint32_t sdst, const void* srcv,
                                             size_t row_stride_elts, int tid) {
    const __nv_bfloat16* src = (const __nv_bfloat16*)srcv;
    const int row = tid >> 2;
    const int cb  = (tid & 3) * 2;
    const __nv_bfloat16* g = src + (size_t)row * row_stride_elts + cb * 8;
#pragma unroll
    for (int c = 0; c < 2; c++)
        cp16(sdst + sw128(row * 128 + (cb + c) * 16), g + c * 8);
}
// 128 rows x 128B with 256 threads
__device__ __forceinline__ void load_tileB128(uint32_t sdst, const void* srcv,
                                              size_t row_stride_elts, int tid) {
    const __half* src = (const __half*)srcv;
    const int row = tid >> 1;
    const int cb  = (tid & 1) * 4;
    const __half* g = src + (size_t)row * row_stride_elts + cb * 8;
#pragma unroll
    for (int c = 0; c < 4; c++)
        cp16(sdst + sw128(row * 128 + (cb + c) * 16), g + c * 8);
}

// ---------------------------------------------------------------------------
// Kernel 1: S = exp(SCALE * X X^T) f16, strict causal, fused row-sum
// ---------------------------------------------------------------------------
__global__ __launch_bounds__(256, 3) void k_qk_mma() {
    const int sb  = blockIdx.x;
    const int tb6 = blockIdx.y;
    const int b   = blockIdx.z;
    if (sb > (tb6 >> 1)) return;

    extern __shared__ __align__(1024) char smem[];
    __shared__ float rsum[64];
    const uint32_t sbase = smem_u32(smem);
    const int tid = threadIdx.x, lane = tid & 31, wid = tid >> 5;
    const int warp_m = wid & 1, warp_n = wid >> 1;

    if (tid < 64) rsum[tid] = 0.f;

    const __nv_bfloat16* A0 = g_Xh + (size_t)(b * T_ + tb6 * 64)  * D_;
    const __nv_bfloat16* B0 = g_Xh + (size_t)(b * T_ + sb * 128)  * D_;

    float c[2][4][4];
#pragma unroll
    for (int mi = 0; mi < 2; mi++)
#pragma unroll
        for (int ni = 0; ni < 4; ni++)
#pragma unroll
            for (int k = 0; k < 4; k++) c[mi][ni][k] = 0.f;

    const int nIter = D_ / 64;
#pragma unroll
    for (int s = 0; s < NSTAGE - 1; s++) {
        const uint32_t st = sbase + s * STAGE_BYTES;
        load_tileA64(st,            A0 + s * 64, D_, tid);
        load_tileB128(st + A_BYTES, B0 + s * 64, D_, tid);
        CP_COMMIT();
    }

    for (int it = 0; it < nIter; ++it) {
        if (it + NSTAGE - 1 < nIter) CP_WAIT(NSTAGE - 2); else CP_WAIT(0);
        __syncthreads();
        if (it + NSTAGE - 1 < nIter) {
            const int ld = it + NSTAGE - 1;
            const uint32_t stb = sbase + (ld % NSTAGE) * STAGE_BYTES;
            load_tileA64(stb,            A0 + ld * 64, D_, tid);
            load_tileB128(stb + A_BYTES, B0 + ld * 64, D_, tid);
            CP_COMMIT();
        }
        const uint32_t st = sbase + (it % NSTAGE) * STAGE_BYTES;
        mma_chunk_qk(st, st + A_BYTES, warp_m, warp_n, lane, c);
    }

    const int quad = lane >> 2, qid = lane & 3;
    const float C2 = 0.045084219f;   // SCALE * log2(e)
#pragma unroll
    for (int mi = 0; mi < 2; mi++) {
        float rs[2] = {0.f, 0.f};
#pragma unroll
        for (int h = 0; h < 2; h++) {
            const int row = warp_m * 32 + mi * 16 + quad + h * 8;
            const int t   = tb6 * 64 + row;
#pragma unroll
            for (int ni = 0; ni < 4; ni++) {
                const int col = warp_n * 32 + ni * 8 + qid * 2;
                const int s0  = sb * 128 + col;
                const float z0 = (s0 + 0 < t) ? c[mi][ni][2 * h + 0] * C2 : -64.f;
                const float z1 = (s0 + 1 < t) ? c[mi][ni][2 * h + 1] * C2 : -64.f;
                __half2 e = h2exp2(__floats2half2_rn(z0, z1));
                *(uint32_t*)(g_Sh + ((size_t)(b * T_ + t)) * T_ + s0) = *(uint32_t*)&e;
                float2 ef = __half22float2(e);
                rs[h] += ef.x + ef.y;
            }
        }
#pragma unroll
        for (int h = 0; h < 2; h++) {
            float v = rs[h];
            v += __shfl_xor_sync(0xFFFFFFFFu, v, 1);
            v += __shfl_xor_sync(0xFFFFFFFFu, v, 2);
            if (qid == 0) {
                const int row = warp_m * 32 + mi * 16 + quad + h * 8;
                atomicAdd(&rsum[row], v);
            }
        }
    }
    __syncthreads();
    if (tid < 64)
        atomicAdd(&g_den[b * T_ + tb6 * 64 + tid], rsum[tid]);
}

// ---------------------------------------------------------------------------
// Kernel 3: context scalars. CTA 128x128, 8 warps of 64x32, 256 thr, 3-stage,
// 2 CTA/SM. f16 MMA. Epilogue: c = acc/den; accumulate per-row sum(c*c),
// sum(x*c) into g_cc/g_xc (NO context tensor store). Heavy tiles first.
// ---------------------------------------------------------------------------
__global__ __launch_bounds__(256) void k_av_mma() {
    const int nb = blockIdx.x;
    const int tb = (int)gridDim.y - 1 - (int)blockIdx.y;   // heavy-first
    const int b  = blockIdx.z;

    extern __shared__ __align__(1024) char smem[];
    __shared__ float s_cc[128], s_xc[128];
    const uint32_t sbase = smem_u32(smem);
    const int tid = threadIdx.x, lane = tid & 31, wid = tid >> 5;
    const int warp_m = wid & 1, warp_n = wid >> 1;

    if (tid < 128) { s_cc[tid] = 0.f; s_xc[tid] = 0.f; }

    const __half* A0 = g_Sh  + (size_t)(b * T_ + tb * 128) * T_;
    const __half* B0 = g_XhT + ((size_t)b * D_ + nb * 128) * T_;

    float c[4][4][4];
#pragma unroll
    for (int mi = 0; mi < 4; mi++)
#pragma unroll
        for (int ni = 0; ni < 4; ni++)
#pragma unroll
            for (int k = 0; k < 4; k++) c[mi][ni][k] = 0.f;

    const int nIter = (tb + 1) * 2;
#pragma unroll
    for (int s = 0; s < AV_NSTAGE - 1; s++) {
        if (s < nIter) {
            const uint32_t st = sbase + s * AV_STAGE;
            load_tileB128(st,         A0 + s * 64, T_, tid);
            load_tileB128(st + 16384, B0 + s * 64, T_, tid);
            CP_COMMIT();
        }
    }

    const int rowsel = lane & 15;
    const int khalf  = (lane >> 4) * 16;

    for (int it = 0; it < nIter; ++it) {
        if (it + AV_NSTAGE - 1 < nIter) CP_WAIT(AV_NSTAGE - 2); else CP_WAIT(0);
        __syncthreads();
        if (it + AV_NSTAGE - 1 < nIter) {
            const int ld = it + AV_NSTAGE - 1;
            const uint32_t stb = sbase + (ld % AV_NSTAGE) * AV_STAGE;
            load_tileB128(stb,         A0 + ld * 64, T_, tid);
            load_tileB128(stb + 16384, B0 + ld * 64, T_, tid);
            CP_COMMIT();
        }
        const uint32_t sA = sbase + (it % AV_NSTAGE) * AV_STAGE;
        const uint32_t sB = sA + 16384;
#pragma unroll
        for (int ks = 0; ks < 4; ks++) {
            const uint32_t kb = ks * 32 + khalf;
            uint32_t a[4][4];
#pragma unroll
            for (int mi = 0; mi < 4; mi++) {
                const uint32_t row = warp_m * 64 + mi * 16 + rowsel;
                ldmx4(a[mi][0], a[mi][1], a[mi][2], a[mi][3],
                      sA + row * 128 + (kb ^ ((row & 7) << 4)));
            }
            uint32_t bf[4][2];
#pragma unroll
            for (int nj = 0; nj < 2; nj++) {
                const uint32_t nrow = warp_n * 32 + nj * 16 + rowsel;
                uint32_t r0, r1, r2, r3;
                ldmx4(r0, r1, r2, r3, sB + nrow * 128 + (kb ^ ((nrow & 7) << 4)));
                bf[nj * 2 + 0][0] = r0; bf[nj * 2 + 1][0] = r1;
                bf[nj * 2 + 0][1] = r2; bf[nj * 2 + 1][1] = r3;
            }
#pragma unroll
            for (int mi = 0; mi < 4; mi++)
#pragma unroll
                for (int ni = 0; ni < 4; ni++)
                    mma_f16(c[mi][ni], a[mi], bf[ni][0], bf[ni][1]);
        }
    }

    // epilogue: per-row cc / xc partials (no context store)
    const int quad = lane >> 2, qid = lane & 3;
#pragma unroll
    for (int mi = 0; mi < 4; mi++) {
#pragma unroll
        for (int h = 0; h < 2; h++) {
            const int row = warp_m * 64 + mi * 16 + quad + h * 8;
            const int t   = tb * 128 + row;
            const float den = g_den[b * T_ + t];
            const float inv = den > 0.f ? 1.f / den : 0.f;
            const __nv_bfloat16* xrow =
                g_Xh + ((size_t)(b * T_ + t)) * D_ + nb * 128;
            float pcc = 0.f, pxc = 0.f;
#pragma unroll
            for (int ni = 0; ni < 4; ni++) {
                const int col = warp_n * 32 + ni * 8 + qid * 2;
                const float c0 = c[mi][ni][2 * h + 0] * inv;
                const float c1 = c[mi][ni][2 * h + 1] * inv;
                const __nv_bfloat162 xb = *(const __nv_bfloat162*)(xrow + col);
                const float x0 = __bfloat162float(xb.x);
                const float x1 = __bfloat162float(xb.y);
                pcc += c0 * c0 + c1 * c1;
                pxc += x0 * c0 + x1 * c1;
            }
            pcc += __shfl_xor_sync(0xFFFFFFFFu, pcc, 1);
            pcc += __shfl_xor_sync(0xFFFFFFFFu, pcc, 2);
            pxc += __shfl_xor_sync(0xFFFFFFFFu, pxc, 1);
            pxc += __shfl_xor_sync(0xFFFFFFFFu, pxc, 2);
            if (qid == 0) {
                atomicAdd(&s_cc[row], pcc);
                atomicAdd(&s_xc[row], pxc);
            }
        }
    }
    __syncthreads();
    if (tid < 128) {
        atomicAdd(&g_cc[b * T_ + tb * 128 + tid], s_cc[tid]);
        atomicAdd(&g_xc[b * T_ + tb * 128 + tid], s_xc[tid]);
    }
}

// ---------------------------------------------------------------------------
// Kernel 4: gate + tanh-GELU. One CTA per (b,t) row; cc/xc precomputed.
// ---------------------------------------------------------------------------
__global__ __launch_bounds__(256) void k_epi(const float* __restrict__ x,
                                             const float* __restrict__ p_la,
                                             const float* __restrict__ p_ls,
                                             float* __restrict__ out) {
    const int row = blockIdx.x;
    const int tid = threadIdx.x;
    const float4 xv = *((const float4*)x + (size_t)row * 256 + tid);

    float xx = xv.x * xv.x + xv.y * xv.y + xv.z * xv.z + xv.w * xv.w;
#pragma unroll
    for (int o = 16; o; o >>= 1)
        xx += __shfl_down_sync(0xFFFFFFFFu, xx, o);

    __shared__ float s_xx[8];
    __shared__ float s_gate;
    const int lane = tid & 31, w = tid >> 5;
    if (lane == 0) s_xx[w] = xx;
    __syncthreads();
    if (tid == 0) {
        float fxx = 0.f;
#pragma unroll
        for (int k = 0; k < 8; k++) fxx += s_xx[k];
        const float fcc = g_cc[row];
        const float fxc = g_xc[row];
        const float nx = fmaxf(sqrtf(fxx), 1e-12f);
        const float nc = fmaxf(sqrtf(fcc), 1e-12f);
        const float cosv = fxc / (nx * nc);
        const float nov  = fminf(fmaxf(1.f - cosv, 0.f), 2.f) * 0.5f;
        const float alpha = softplusf_(*p_la);
        const float sigma = softplusf_(*p_ls);
        s_gate = 1.f + alpha * tanhf(sigma * nov);
    }
    __syncthreads();
    const float g = s_gate;

    float4 o;
    o.x = gelu_tanh_(xv.x * g);
    o.y = gelu_tanh_(xv.y * g);
    o.z = gelu_tanh_(xv.z * g);
    o.w = gelu_tanh_(xv.w * g);
    *((float4*)out + (size_t)row * 256 + tid) = o;
}

// ---------------------------------------------------------------------------
extern "C" void kernel_launch(void* const* d_in, const int* in_sizes, int n_in,
                              void* d_out, int out_size) {
    const float* x  = (const float*)d_in[0];
    const float* la = (const float*)d_in[1];
    const float* ls = (const float*)d_in[2];
    float* out = (float*)d_out;

    const int qk_smem = NSTAGE * STAGE_BYTES;      // 73728
    const int av_smem = AV_NSTAGE * AV_STAGE;      // 98304
    cudaFuncSetAttribute(k_qk_mma, cudaFuncAttributeMaxDynamicSharedMemorySize, qk_smem);
    cudaFuncSetAttribute(k_av_mma, cudaFuncAttributeMaxDynamicSharedMemorySize, av_smem);

    k_zero<<<(B_ * T_ + 1023) / 1024, 1024>>>();

    dim3 gc(T_ / 32, D_ / 32, B_);
    k_cvt<<<gc, dim3(16, 16)>>>(x);

    dim3 g1(16, 32, B_);
    k_qk_mma<<<g1, 256, qk_smem>>>();

    dim3 g3(8, 16, B_);
    k_av_mma<<<g3, 256, av_smem>>>();

    k_epi<<<B_ * T_, 256>>>(x, la, ls, out);
}

// round 13
// speedup vs baseline: 1.1944x; 1.0187x over previous
#include <cuda_runtime.h>
#include <cuda_bf16.h>
#include <cuda_fp16.h>
#include <stdint.h>

#define B_ 8
#define T_ 2048
#define D_ 1024
#define SCALE_ 0.03125f   // 1/sqrt(1024)

// k_qk config
#define NSTAGE 3
#define A_BYTES 8192
#define B_BYTES 16384
#define STAGE_BYTES (A_BYTES + B_BYTES)   // 24576

// k_av config (R4/R8 proven shape)
#define AV_NSTAGE 3
#define AV_STAGE 32768      // A 128x128B + B 128x128B

// ---------------------------------------------------------------------------
// Scratch
// ---------------------------------------------------------------------------
__device__ __nv_bfloat16 g_Xh [(size_t)B_ * T_ * D_];   // x bf16
__device__ __half        g_XhT[(size_t)B_ * D_ * T_];   // x^T f16
__device__ __half        g_Sh [(size_t)B_ * T_ * T_];   // exp(masked logits), f16
__device__ __half        g_Ch [(size_t)B_ * T_ * D_];   // context f16
__device__ float         g_den[B_ * T_];                // softmax denominators

// ---------------------------------------------------------------------------
// Helpers
// ---------------------------------------------------------------------------
__device__ __forceinline__ uint32_t smem_u32(const void* p) {
    uint32_t a;
    asm("{ .reg .u64 t; cvta.to.shared.u64 t, %1; cvt.u32.u64 %0, t; }"
        : "=r"(a) : "l"(p));
    return a;
}

__device__ __forceinline__ void cp16(uint32_t dst, const void* src) {
    asm volatile("cp.async.cg.shared.global [%0], [%1], 16;"
                 :: "r"(dst), "l"(src) : "memory");
}
#define CP_COMMIT() asm volatile("cp.async.commit_group;" ::: "memory")
#define CP_WAIT(N)  asm volatile("cp.async.wait_group %0;" :: "n"(N) : "memory")

__device__ __forceinline__ void ldmx4(uint32_t& r0, uint32_t& r1,
                                      uint32_t& r2, uint32_t& r3, uint32_t addr) {
    asm volatile("ldmatrix.sync.aligned.m8n8.x4.shared.b16 {%0,%1,%2,%3}, [%4];"
                 : "=r"(r0), "=r"(r1), "=r"(r2), "=r"(r3) : "r"(addr));
}

__device__ __forceinline__ void mma_bf16(float* c, const uint32_t* a,
                                         uint32_t b0, uint32_t b1) {
    asm volatile(
        "mma.sync.aligned.m16n8k16.row.col.f32.bf16.bf16.f32 "
        "{%0,%1,%2,%3}, {%4,%5,%6,%7}, {%8,%9}, {%0,%1,%2,%3};"
        : "+f"(c[0]), "+f"(c[1]), "+f"(c[2]), "+f"(c[3])
        : "r"(a[0]), "r"(a[1]), "r"(a[2]), "r"(a[3]), "r"(b0), "r"(b1));
}

__device__ __forceinline__ void mma_f16(float* c, const uint32_t* a,
                                        uint32_t b0, uint32_t b1) {
    asm volatile(
        "mma.sync.aligned.m16n8k16.row.col.f32.f16.f16.f32 "
        "{%0,%1,%2,%3}, {%4,%5,%6,%7}, {%8,%9}, {%0,%1,%2,%3};"
        : "+f"(c[0]), "+f"(c[1]), "+f"(c[2]), "+f"(c[3])
        : "r"(a[0]), "r"(a[1]), "r"(a[2]), "r"(a[3]), "r"(b0), "r"(b1));
}

__device__ __forceinline__ uint32_t sw128(uint32_t off) {
    return off ^ ((off >> 3) & 0x70);
}

__device__ __forceinline__ float softplusf_(float v) {
    return v > 20.f ? v : log1pf(__expf(v));
}
__device__ __forceinline__ float gelu_tanh_(float v) {
    float u = 0.7978845608028654f * (v + 0.044715f * v * v * v);
    return 0.5f * v * (1.f + tanhf(u));
}

// ---------------------------------------------------------------------------
// Kernel Z: zero denominators
// ---------------------------------------------------------------------------
__global__ void k_zero() {
    const int i = blockIdx.x * 1024 + threadIdx.x;
    if (i < B_ * T_) g_den[i] = 0.f;
}

// ---------------------------------------------------------------------------
// Kernel 0: convert x -> bf16 row-major + f16 transposed
// ---------------------------------------------------------------------------
__global__ __launch_bounds__(256) void k_cvt(const float* __restrict__ x) {
    __shared__ float tile[32][33];
    const int b  = blockIdx.z;
    const int t0 = blockIdx.x * 32;
    const int d0 = blockIdx.y * 32;
    const int lx = threadIdx.x;
    const int ly = threadIdx.y;
    const float* X = x + (size_t)b * T_ * D_;

#pragma unroll
    for (int r = 0; r < 2; r++) {
        const int t = t0 + ly + r * 16;
        const int d = d0 + lx * 2;
        float2 v = *(const float2*)(X + (size_t)t * D_ + d);
        __nv_bfloat162 h = __floats2bfloat162_rn(v.x, v.y);
        *(uint32_t*)(g_Xh + (size_t)(b * T_ + t) * D_ + d) = *(uint32_t*)&h;
        tile[ly + r * 16][lx * 2 + 0] = v.x;
        tile[ly + r * 16][lx * 2 + 1] = v.y;
    }
    __syncthreads();
#pragma unroll
    for (int r = 0; r < 2; r++) {
        const int d  = d0 + ly + r * 16;
        const int tp = lx * 2;
        __half2 h = __floats2half2_rn(tile[tp + 0][ly + r * 16],
                                      tile[tp + 1][ly + r * 16]);
        *(uint32_t*)(g_XhT + ((size_t)b * D_ + d) * T_ + t0 + tp) = *(uint32_t*)&h;
    }
}

// ---------------------------------------------------------------------------
// k_qk MMA core: CTA 64x128, 8 warps 2m x 4n of 32x32, bf16
// ---------------------------------------------------------------------------
__device__ __forceinline__ void mma_chunk_qk(uint32_t sA, uint32_t sB,
                                             int warp_m, int warp_n, int lane,
                                             float c[2][4][4]) {
    const int rowsel = lane & 15;
    const int khalf  = (lane >> 4) * 16;
    const uint32_t a0 = sA + (warp_m * 32 + 0  + rowsel) * 128;
    const uint32_t a1 = sA + (warp_m * 32 + 16 + rowsel) * 128;
    const uint32_t b0a = sB + (warp_n * 32 + 0  + rowsel) * 128;
    const uint32_t b1a = sB + (warp_n * 32 + 16 + rowsel) * 128;
    const uint32_t xa0 = ((warp_m * 32 + 0  + rowsel) & 7) << 4;
    const uint32_t xa1 = ((warp_m * 32 + 16 + rowsel) & 7) << 4;
    const uint32_t xb0 = ((warp_n * 32 + 0  + rowsel) & 7) << 4;
    const uint32_t xb1 = ((warp_n * 32 + 16 + rowsel) & 7) << 4;
#pragma unroll
    for (int ks = 0; ks < 4; ks++) {
        const uint32_t kb = ks * 32 + khalf;
        uint32_t a[2][4];
        ldmx4(a[0][0], a[0][1], a[0][2], a[0][3], a0 + (kb ^ xa0));
        ldmx4(a[1][0], a[1][1], a[1][2], a[1][3], a1 + (kb ^ xa1));
        uint32_t b[4][2];
        {
            uint32_t r0, r1, r2, r3;
            ldmx4(r0, r1, r2, r3, b0a + (kb ^ xb0));
            b[0][0] = r0; b[1][0] = r1; b[0][1] = r2; b[1][1] = r3;
            ldmx4(r0, r1, r2, r3, b1a + (kb ^ xb1));
            b[2][0] = r0; b[3][0] = r1; b[2][1] = r2; b[3][1] = r3;
        }
#pragma unroll
        for (int mi = 0; mi < 2; mi++)
#pragma unroll
            for (int ni = 0; ni < 4; ni++)
                mma_bf16(c[mi][ni], a[mi], b[ni][0], b[ni][1]);
    }
}

__device__ __forceinline__ void load_tileA64(uint32_t sdst, const void* srcv,
                                             size_t row_stride_elts, int tid) {
    const __nv_bfloat16* src = (const __nv_bfloat16*)srcv;
    const int row = tid >> 2;
    const int cb  = (tid & 3) * 2;
    const __nv_bfloat16* g = src + (size_t)row * row_stride_elts + cb * 8;
#pragma unroll
    for (int c = 0; c < 2; c++)
        cp16(sdst + sw128(row * 128 + (cb + c) * 16), g + c * 8);
}
// 128 rows x 128B with 256 threads
__device__ __forceinline__ void load_tileB128(uint32_t sdst, const void* srcv,
                                              size_t row_stride_elts, int tid) {
    const __half* src = (const __half*)srcv;
    const int row = tid >> 1;
    const int cb  = (tid & 1) * 4;
    const __half* g = src + (size_t)row * row_stride_elts + cb * 8;
#pragma unroll
    for (int c = 0; c < 4; c++)
        cp16(sdst + sw128(row * 128 + (cb + c) * 16), g + c * 8);
}

// ---------------------------------------------------------------------------
// Kernel 1: S = exp(SCALE * X X^T) f16, strict causal, fused row-sum
// (mask applied to exp argument; -64 -> exp2 == 0 exactly in f16)
// ---------------------------------------------------------------------------
__global__ __launch_bounds__(256, 3) void k_qk_mma() {
    const int sb  = blockIdx.x;
    const int tb6 = blockIdx.y;
    const int b   = blockIdx.z;
    if (sb > (tb6 >> 1)) return;

    extern __shared__ __align__(1024) char smem[];
    __shared__ float rsum[64];
    const uint32_t sbase = smem_u32(smem);
    const int tid = threadIdx.x, lane = tid & 31, wid = tid >> 5;
    const int warp_m = wid & 1, warp_n = wid >> 1;

    if (tid < 64) rsum[tid] = 0.f;

    const __nv_bfloat16* A0 = g_Xh + (size_t)(b * T_ + tb6 * 64)  * D_;
    const __nv_bfloat16* B0 = g_Xh + (size_t)(b * T_ + sb * 128)  * D_;

    float c[2][4][4];
#pragma unroll
    for (int mi = 0; mi < 2; mi++)
#pragma unroll
        for (int ni = 0; ni < 4; ni++)
#pragma unroll
            for (int k = 0; k < 4; k++) c[mi][ni][k] = 0.f;

    const int nIter = D_ / 64;
#pragma unroll
    for (int s = 0; s < NSTAGE - 1; s++) {
        const uint32_t st = sbase + s * STAGE_BYTES;
        load_tileA64(st,            A0 + s * 64, D_, tid);
        load_tileB128(st + A_BYTES, B0 + s * 64, D_, tid);
        CP_COMMIT();
    }

    for (int it = 0; it < nIter; ++it) {
        if (it + NSTAGE - 1 < nIter) CP_WAIT(NSTAGE - 2); else CP_WAIT(0);
        __syncthreads();
        if (it + NSTAGE - 1 < nIter) {
            const int ld = it + NSTAGE - 1;
            const uint32_t stb = sbase + (ld % NSTAGE) * STAGE_BYTES;
            load_tileA64(stb,            A0 + ld * 64, D_, tid);
            load_tileB128(stb + A_BYTES, B0 + ld * 64, D_, tid);
            CP_COMMIT();
        }
        const uint32_t st = sbase + (it % NSTAGE) * STAGE_BYTES;
        mma_chunk_qk(st, st + A_BYTES, warp_m, warp_n, lane, c);
    }

    const int quad = lane >> 2, qid = lane & 3;
    const float C2 = 0.045084219f;   // SCALE * log2(e)
#pragma unroll
    for (int mi = 0; mi < 2; mi++) {
        float rs[2] = {0.f, 0.f};
#pragma unroll
        for (int h = 0; h < 2; h++) {
            const int row = warp_m * 32 + mi * 16 + quad + h * 8;
            const int t   = tb6 * 64 + row;
#pragma unroll
            for (int ni = 0; ni < 4; ni++) {
                const int col = warp_n * 32 + ni * 8 + qid * 2;
                const int s0  = sb * 128 + col;
                const float z0 = (s0 + 0 < t) ? c[mi][ni][2 * h + 0] * C2 : -64.f;
                const float z1 = (s0 + 1 < t) ? c[mi][ni][2 * h + 1] * C2 : -64.f;
                __half2 e = h2exp2(__floats2half2_rn(z0, z1));
                *(uint32_t*)(g_Sh + ((size_t)(b * T_ + t)) * T_ + s0) = *(uint32_t*)&e;
                float2 ef = __half22float2(e);
                rs[h] += ef.x + ef.y;
            }
        }
#pragma unroll
        for (int h = 0; h < 2; h++) {
            float v = rs[h];
            v += __shfl_xor_sync(0xFFFFFFFFu, v, 1);
            v += __shfl_xor_sync(0xFFFFFFFFu, v, 2);
            if (qid == 0) {
                const int row = warp_m * 32 + mi * 16 + quad + h * 8;
                atomicAdd(&rsum[row], v);
            }
        }
    }
    __syncthreads();
    if (tid < 64)
        atomicAdd(&g_den[b * T_ + tb6 * 64 + tid], rsum[tid]);
}

// ---------------------------------------------------------------------------
// Kernel 3: context = (S @ X) / den. R8 shape: CTA 128x128, 8 warps of 64x32,
// 256 thr, 3-stage, 2 CTA/SM. f16 MMA, f16 C store. Heavy tiles first.
// ---------------------------------------------------------------------------
__global__ __launch_bounds__(256) void k_av_mma() {
    const int nb = blockIdx.x;
    const int tb = (int)gridDim.y - 1 - (int)blockIdx.y;   // heavy-first
    const int b  = blockIdx.z;

    extern __shared__ __align__(1024) char smem[];
    const uint32_t sbase = smem_u32(smem);
    const int tid = threadIdx.x, lane = tid & 31, wid = tid >> 5;
    const int warp_m = wid & 1, warp_n = wid >> 1;

    const __half* A0 = g_Sh  + (size_t)(b * T_ + tb * 128) * T_;
    const __half* B0 = g_XhT + ((size_t)b * D_ + nb * 128) * T_;

    float c[4][4][4];
#pragma unroll
    for (int mi = 0; mi < 4; mi++)
#pragma unroll
        for (int ni = 0; ni < 4; ni++)
#pragma unroll
            for (int k = 0; k < 4; k++) c[mi][ni][k] = 0.f;

    const int nIter = (tb + 1) * 2;
#pragma unroll
    for (int s = 0; s < AV_NSTAGE - 1; s++) {
        if (s < nIter) {
            const uint32_t st = sbase + s * AV_STAGE;
            load_tileB128(st,         A0 + s * 64, T_, tid);
            load_tileB128(st + 16384, B0 + s * 64, T_, tid);
            CP_COMMIT();
        }
    }

    const int rowsel = lane & 15;
    const int khalf  = (lane >> 4) * 16;

    for (int it = 0; it < nIter; ++it) {
        if (it + AV_NSTAGE - 1 < nIter) CP_WAIT(AV_NSTAGE - 2); else CP_WAIT(0);
        __syncthreads();
        if (it + AV_NSTAGE - 1 < nIter) {
            const int ld = it + AV_NSTAGE - 1;
            const uint32_t stb = sbase + (ld % AV_NSTAGE) * AV_STAGE;
            load_tileB128(stb,         A0 + ld * 64, T_, tid);
            load_tileB128(stb + 16384, B0 + ld * 64, T_, tid);
            CP_COMMIT();
        }
        const uint32_t sA = sbase + (it % AV_NSTAGE) * AV_STAGE;
        const uint32_t sB = sA + 16384;
#pragma unroll
        for (int ks = 0; ks < 4; ks++) {
            const uint32_t kb = ks * 32 + khalf;
            uint32_t a[4][4];
#pragma unroll
            for (int mi = 0; mi < 4; mi++) {
                const uint32_t row = warp_m * 64 + mi * 16 + rowsel;
                ldmx4(a[mi][0], a[mi][1], a[mi][2], a[mi][3],
                      sA + row * 128 + (kb ^ ((row & 7) << 4)));
            }
            uint32_t bf[4][2];
#pragma unroll
            for (int nj = 0; nj < 2; nj++) {
                const uint32_t nrow = warp_n * 32 + nj * 16 + rowsel;
                uint32_t r0, r1, r2, r3;
                ldmx4(r0, r1, r2, r3, sB + nrow * 128 + (kb ^ ((nrow & 7) << 4)));
                bf[nj * 2 + 0][0] = r0; bf[nj * 2 + 1][0] = r1;
                bf[nj * 2 + 0][1] = r2; bf[nj * 2 + 1][1] = r3;
            }
#pragma unroll
            for (int mi = 0; mi < 4; mi++)
#pragma unroll
                for (int ni = 0; ni < 4; ni++)
                    mma_f16(c[mi][ni], a[mi], bf[ni][0], bf[ni][1]);
        }
    }

    // epilogue: divide by denom, f16 store
    const int quad = lane >> 2, qid = lane & 3;
#pragma unroll
    for (int mi = 0; mi < 4; mi++) {
#pragma unroll
        for (int h = 0; h < 2; h++) {
            const int row = warp_m * 64 + mi * 16 + quad + h * 8;
            const int t   = tb * 128 + row;
            const float den = g_den[b * T_ + t];
            const float inv = den > 0.f ? 1.f / den : 0.f;
            __half* crow = g_Ch + ((size_t)(b * T_ + t)) * D_ + nb * 128;
#pragma unroll
            for (int ni = 0; ni < 4; ni++) {
                const int col = warp_n * 32 + ni * 8 + qid * 2;
                __half2 hv = __floats2half2_rn(c[mi][ni][2 * h + 0] * inv,
                                               c[mi][ni][2 * h + 1] * inv);
                *(uint32_t*)(crow + col) = *(uint32_t*)&hv;
            }
        }
    }
}

// ---------------------------------------------------------------------------
// Kernel 4: cosine / novelty / gate / tanh-GELU (C in f16)
// ---------------------------------------------------------------------------
__global__ __launch_bounds__(256) void k_epi(const float* __restrict__ x,
                                             const float* __restrict__ p_la,
                                             const float* __restrict__ p_ls,
                                             float* __restrict__ out) {
    const int row = blockIdx.x;
    const int tid = threadIdx.x;
    const float4 xv = *((const float4*)x + (size_t)row * 256 + tid);
    const uint2 cu  = *((const uint2*)g_Ch + (size_t)row * 256 + tid);
    float2 c01 = __half22float2(*(const __half2*)&cu.x);
    float2 c23 = __half22float2(*(const __half2*)&cu.y);

    float xx = xv.x * xv.x + xv.y * xv.y + xv.z * xv.z + xv.w * xv.w;
    float cc = c01.x * c01.x + c01.y * c01.y + c23.x * c23.x + c23.y * c23.y;
    float xc = xv.x * c01.x + xv.y * c01.y + xv.z * c23.x + xv.w * c23.y;

#pragma unroll
    for (int o = 16; o; o >>= 1) {
        xx += __shfl_down_sync(0xFFFFFFFFu, xx, o);
        cc += __shfl_down_sync(0xFFFFFFFFu, cc, o);
        xc += __shfl_down_sync(0xFFFFFFFFu, xc, o);
    }

    __shared__ float s_xx[8], s_cc[8], s_xc[8];
    __shared__ float s_gate;
    const int lane = tid & 31, w = tid >> 5;
    if (lane == 0) { s_xx[w] = xx; s_cc[w] = cc; s_xc[w] = xc; }
    __syncthreads();
    if (tid == 0) {
        float fxx = 0.f, fcc = 0.f, fxc = 0.f;
#pragma unroll
        for (int k = 0; k < 8; k++) { fxx += s_xx[k]; fcc += s_cc[k]; fxc += s_xc[k]; }
        const float nx = fmaxf(sqrtf(fxx), 1e-12f);
        const float nc = fmaxf(sqrtf(fcc), 1e-12f);
        const float cosv = fxc / (nx * nc);
        const float nov  = fminf(fmaxf(1.f - cosv, 0.f), 2.f) * 0.5f;
        const float alpha = softplusf_(*p_la);
        const float sigma = softplusf_(*p_ls);
        s_gate = 1.f + alpha * tanhf(sigma * nov);
    }
    __syncthreads();
    const float g = s_gate;

    float4 o;
    o.x = gelu_tanh_(xv.x * g);
    o.y = gelu_tanh_(xv.y * g);
    o.z = gelu_tanh_(xv.z * g);
    o.w = gelu_tanh_(xv.w * g);
    *((float4*)out + (size_t)row * 256 + tid) = o;
}

// ---------------------------------------------------------------------------
extern "C" void kernel_launch(void* const* d_in, const int* in_sizes, int n_in,
                              void* d_out, int out_size) {
    const float* x  = (const float*)d_in[0];
    const float* la = (const float*)d_in[1];
    const float* ls = (const float*)d_in[2];
    float* out = (float*)d_out;

    const int qk_smem = NSTAGE * STAGE_BYTES;      // 73728
    const int av_smem = AV_NSTAGE * AV_STAGE;      // 98304
    cudaFuncSetAttribute(k_qk_mma, cudaFuncAttributeMaxDynamicSharedMemorySize, qk_smem);
    cudaFuncSetAttribute(k_av_mma, cudaFuncAttributeMaxDynamicSharedMemorySize, av_smem);

    k_zero<<<(B_ * T_ + 1023) / 1024, 1024>>>();

    dim3 gc(T_ / 32, D_ / 32, B_);
    k_cvt<<<gc, dim3(16, 16)>>>(x);

    dim3 g1(16, 32, B_);
    k_qk_mma<<<g1, 256, qk_smem>>>();

    dim3 g3(8, 16, B_);
    k_av_mma<<<g3, 256, av_smem>>>();

    k_epi<<<B_ * T_, 256>>>(x, la, ls, out);
}

// round 14
// speedup vs baseline: 1.5803x; 1.3231x over previous
#include <cuda_runtime.h>
#include <cuda_bf16.h>
#include <cuda_fp16.h>
#include <stdint.h>

#define B_ 8
#define T_ 2048
#define D_ 1024
#define SCALE_ 0.03125f   // 1/sqrt(1024)

// k_qk: stage = A tile 8KB + B tiles 16KB
#define QK_STAGE 24576
// k_av: stage = S tile 16KB + XT tile 16KB
#define AV_STAGE 32768

// ---------------------------------------------------------------------------
// Scratch — tiled, pre-swizzled layouts
//   g_Xh : bf16 X tiles  [b][t64:32][kc:16] of 64r x 64c (8KB each)
//   g_St : f16  S tiles  [b][tb:16][kc:32]  of 128r x 64c (16KB each)
//   g_XTt: f16  XT tiles [b][nb:8][kc:32]   of 128r(d) x 64c(t) (16KB each)
// ---------------------------------------------------------------------------
__device__ __nv_bfloat16 g_Xh [(size_t)B_ * 32 * 16 * 4096];
__device__ __half        g_St [(size_t)B_ * 16 * 32 * 8192];
__device__ __half        g_XTt[(size_t)B_ * 8  * 32 * 8192];
__device__ __half        g_Ch [(size_t)B_ * T_ * D_];     // context f16 (row-major)
__device__ float         g_den[B_ * T_];

// ---------------------------------------------------------------------------
// Helpers
// ---------------------------------------------------------------------------
__device__ __forceinline__ uint32_t smem_u32(const void* p) {
    uint32_t a;
    asm("{ .reg .u64 t; cvta.to.shared.u64 t, %1; cvt.u32.u64 %0, t; }"
        : "=r"(a) : "l"(p));
    return a;
}

#define MBAR_INIT(addr, cnt) \
    asm volatile("mbarrier.init.shared.b64 [%0], %1;" :: "r"(addr), "r"(cnt) : "memory")

__device__ __forceinline__ void bar_expect(uint32_t mbar, uint32_t bytes) {
    asm volatile("mbarrier.arrive.expect_tx.shared.b64 _, [%0], %1;"
                 :: "r"(mbar), "r"(bytes) : "memory");
}

__device__ __forceinline__ void bar_wait(uint32_t mbar, uint32_t phase) {
    asm volatile(
        "{\n\t.reg .pred P;\n"
        "W%=:\n\t"
        "mbarrier.try_wait.parity.shared.b64 P, [%0], %1;\n\t"
        "@!P bra W%=;\n\t}"
        :: "r"(mbar), "r"(phase) : "memory");
}

__device__ __forceinline__ void bulk_ld(uint32_t dst, const void* src,
                                        uint32_t bytes, uint32_t mbar) {
    asm volatile(
        "cp.async.bulk.shared::cluster.global.mbarrier::complete_tx::bytes "
        "[%0], [%1], %2, [%3];"
        :: "r"(dst), "l"(src), "r"(bytes), "r"(mbar) : "memory");
}

__device__ __forceinline__ void ldmx4(uint32_t& r0, uint32_t& r1,
                                      uint32_t& r2, uint32_t& r3, uint32_t addr) {
    asm volatile("ldmatrix.sync.aligned.m8n8.x4.shared.b16 {%0,%1,%2,%3}, [%4];"
                 : "=r"(r0), "=r"(r1), "=r"(r2), "=r"(r3) : "r"(addr));
}

__device__ __forceinline__ void mma_bf16(float* c, const uint32_t* a,
                                         uint32_t b0, uint32_t b1) {
    asm volatile(
        "mma.sync.aligned.m16n8k16.row.col.f32.bf16.bf16.f32 "
        "{%0,%1,%2,%3}, {%4,%5,%6,%7}, {%8,%9}, {%0,%1,%2,%3};"
        : "+f"(c[0]), "+f"(c[1]), "+f"(c[2]), "+f"(c[3])
        : "r"(a[0]), "r"(a[1]), "r"(a[2]), "r"(a[3]), "r"(b0), "r"(b1));
}

__device__ __forceinline__ void mma_f16(float* c, const uint32_t* a,
                                        uint32_t b0, uint32_t b1) {
    asm volatile(
        "mma.sync.aligned.m16n8k16.row.col.f32.f16.f16.f32 "
        "{%0,%1,%2,%3}, {%4,%5,%6,%7}, {%8,%9}, {%0,%1,%2,%3};"
        : "+f"(c[0]), "+f"(c[1]), "+f"(c[2]), "+f"(c[3])
        : "r"(a[0]), "r"(a[1]), "r"(a[2]), "r"(a[3]), "r"(b0), "r"(b1));
}

__device__ __forceinline__ uint32_t sw128(uint32_t off) {
    return off ^ ((off >> 3) & 0x70);
}

__device__ __forceinline__ float softplusf_(float v) {
    return v > 20.f ? v : log1pf(__expf(v));
}
__device__ __forceinline__ float gelu_tanh_(float v) {
    float u = 0.7978845608028654f * (v + 0.044715f * v * v * v);
    return 0.5f * v * (1.f + tanhf(u));
}

// ---------------------------------------------------------------------------
// Kernel Z: zero denominators
// ---------------------------------------------------------------------------
__global__ void k_zero() {
    const int i = blockIdx.x * 1024 + threadIdx.x;
    if (i < B_ * T_) g_den[i] = 0.f;
}

// ---------------------------------------------------------------------------
// Kernel 0: convert x -> tiled bf16 X tiles + tiled f16 XT tiles
// ---------------------------------------------------------------------------
__global__ __launch_bounds__(256) void k_cvt(const float* __restrict__ x) {
    __shared__ float tile[32][33];
    const int b  = blockIdx.z;
    const int t0 = blockIdx.x * 32;
    const int d0 = blockIdx.y * 32;
    const int lx = threadIdx.x;
    const int ly = threadIdx.y;
    const float* X = x + (size_t)b * T_ * D_;

#pragma unroll
    for (int r = 0; r < 2; r++) {
        const int t = t0 + ly + r * 16;
        const int d = d0 + lx * 2;
        float2 v = *(const float2*)(X + (size_t)t * D_ + d);
        __nv_bfloat162 h = __floats2bfloat162_rn(v.x, v.y);
        // Xh tile (b, t>>6, d>>6), within: sw128((t&63)*128 + (d&63)*2)
        const size_t tile_idx = (size_t)((b * 32 + (t >> 6)) * 16 + (d >> 6));
        char* dst = (char*)g_Xh + tile_idx * 8192
                  + sw128((uint32_t)((t & 63) * 128 + (d & 63) * 2));
        *(uint32_t*)dst = *(uint32_t*)&h;
        tile[ly + r * 16][lx * 2 + 0] = v.x;
        tile[ly + r * 16][lx * 2 + 1] = v.y;
    }
    __syncthreads();
#pragma unroll
    for (int r = 0; r < 2; r++) {
        const int d  = d0 + ly + r * 16;
        const int tp = t0 + lx * 2;
        __half2 h = __floats2half2_rn(tile[lx * 2 + 0][ly + r * 16],
                                      tile[lx * 2 + 1][ly + r * 16]);
        // XT tile (b, d>>7, t>>6), within: sw128((d&127)*128 + (t&63)*2)
        const size_t tile_idx = (size_t)((b * 8 + (d >> 7)) * 32 + (tp >> 6));
        char* dst = (char*)g_XTt + tile_idx * 16384
                  + sw128((uint32_t)((d & 127) * 128 + (tp & 63) * 2));
        *(uint32_t*)dst = *(uint32_t*)&h;
    }
}

// ---------------------------------------------------------------------------
// k_qk MMA core: CTA 64x128, 8 warps 2m x 4n of 32x32, bf16
// ---------------------------------------------------------------------------
__device__ __forceinline__ void mma_chunk_qk(uint32_t sA, uint32_t sB,
                                             int warp_m, int warp_n, int lane,
                                             float c[2][4][4]) {
    const int rowsel = lane & 15;
    const int khalf  = (lane >> 4) * 16;
    const uint32_t a0 = sA + (warp_m * 32 + 0  + rowsel) * 128;
    const uint32_t a1 = sA + (warp_m * 32 + 16 + rowsel) * 128;
    const uint32_t b0a = sB + (warp_n * 32 + 0  + rowsel) * 128;
    const uint32_t b1a = sB + (warp_n * 32 + 16 + rowsel) * 128;
    const uint32_t xa0 = ((warp_m * 32 + 0  + rowsel) & 7) << 4;
    const uint32_t xa1 = ((warp_m * 32 + 16 + rowsel) & 7) << 4;
    const uint32_t xb0 = ((warp_n * 32 + 0  + rowsel) & 7) << 4;
    const uint32_t xb1 = ((warp_n * 32 + 16 + rowsel) & 7) << 4;
#pragma unroll
    for (int ks = 0; ks < 4; ks++) {
        const uint32_t kb = ks * 32 + khalf;
        uint32_t a[2][4];
        ldmx4(a[0][0], a[0][1], a[0][2], a[0][3], a0 + (kb ^ xa0));
        ldmx4(a[1][0], a[1][1], a[1][2], a[1][3], a1 + (kb ^ xa1));
        uint32_t b[4][2];
        {
            uint32_t r0, r1, r2, r3;
            ldmx4(r0, r1, r2, r3, b0a + (kb ^ xb0));
            b[0][0] = r0; b[1][0] = r1; b[0][1] = r2; b[1][1] = r3;
            ldmx4(r0, r1, r2, r3, b1a + (kb ^ xb1));
            b[2][0] = r0; b[3][0] = r1; b[2][1] = r2; b[3][1] = r3;
        }
#pragma unroll
        for (int mi = 0; mi < 2; mi++)
#pragma unroll
            for (int ni = 0; ni < 4; ni++)
                mma_bf16(c[mi][ni], a[mi], b[ni][0], b[ni][1]);
    }
}

// ---------------------------------------------------------------------------
// Kernel 1: S = exp(SCALE * X X^T) f16 tiled, strict causal, fused row-sum.
// Bulk-copy pipeline: 3 bulk loads/iter instead of 1536 cp.async.
// ---------------------------------------------------------------------------
__global__ __launch_bounds__(256, 3) void k_qk_mma() {
    const int sb  = blockIdx.x;
    const int tb6 = blockIdx.y;
    const int b   = blockIdx.z;
    if (sb > (tb6 >> 1)) return;

    extern __shared__ __align__(1024) char smem[];
    __shared__ __align__(8) uint64_t bars[3];
    __shared__ float rsum[64];
    const uint32_t sbase = smem_u32(smem);
    const int tid = threadIdx.x, lane = tid & 31, wid = tid >> 5;
    const int warp_m = wid & 1, warp_n = wid >> 1;

    if (tid < 64) rsum[tid] = 0.f;
    if (tid == 0) {
#pragma unroll
        for (int s = 0; s < 3; s++) MBAR_INIT(smem_u32(&bars[s]), 1);
    }
    __syncthreads();

    // global tile bases
    const char* XA = (const char*)g_Xh + (size_t)((b * 32 + tb6) * 16) * 8192;
    const char* XB0 = (const char*)g_Xh + (size_t)((b * 32 + 2 * sb) * 16) * 8192;
    const char* XB1 = (const char*)g_Xh + (size_t)((b * 32 + 2 * sb + 1) * 16) * 8192;

    float c[2][4][4];
#pragma unroll
    for (int mi = 0; mi < 2; mi++)
#pragma unroll
        for (int ni = 0; ni < 4; ni++)
#pragma unroll
            for (int k = 0; k < 4; k++) c[mi][ni][k] = 0.f;

    const int nIter = 16;   // kc 0..15 (D=1024)
    if (tid == 0) {
#pragma unroll
        for (int s = 0; s < 2; s++) {
            const uint32_t mb = smem_u32(&bars[s]);
            const uint32_t st = sbase + s * QK_STAGE;
            bar_expect(mb, QK_STAGE);
            bulk_ld(st,         XA  + (size_t)s * 8192, 8192, mb);
            bulk_ld(st + 8192,  XB0 + (size_t)s * 8192, 8192, mb);
            bulk_ld(st + 16384, XB1 + (size_t)s * 8192, 8192, mb);
        }
    }

    for (int it = 0; it < nIter; ++it) {
        bar_wait(smem_u32(&bars[it % 3]), (uint32_t)((it / 3) & 1));
        __syncthreads();
        if (it + 2 < nIter && tid == 0) {
            const int ld = it + 2;
            const int s  = ld % 3;
            const uint32_t mb = smem_u32(&bars[s]);
            const uint32_t st = sbase + s * QK_STAGE;
            bar_expect(mb, QK_STAGE);
            bulk_ld(st,         XA  + (size_t)ld * 8192, 8192, mb);
            bulk_ld(st + 8192,  XB0 + (size_t)ld * 8192, 8192, mb);
            bulk_ld(st + 16384, XB1 + (size_t)ld * 8192, 8192, mb);
        }
        const uint32_t st = sbase + (it % 3) * QK_STAGE;
        mma_chunk_qk(st, st + 8192, warp_m, warp_n, lane, c);
    }

    // epilogue: masked packed exp2 -> f16 tiled S store + fused row-sum
    const int quad = lane >> 2, qid = lane & 3;
    const float C2 = 0.045084219f;   // SCALE * log2(e)
    const size_t srow_base = (size_t)((b * 16 + (tb6 >> 1)) * 32);
#pragma unroll
    for (int mi = 0; mi < 2; mi++) {
        float rs[2] = {0.f, 0.f};
#pragma unroll
        for (int h = 0; h < 2; h++) {
            const int row = warp_m * 32 + mi * 16 + quad + h * 8;
            const int t   = tb6 * 64 + row;
            const int row_local = (tb6 & 1) * 64 + row;
#pragma unroll
            for (int ni = 0; ni < 4; ni++) {
                const int col = warp_n * 32 + ni * 8 + qid * 2;   // 0..127
                const int s0  = sb * 128 + col;
                const float z0 = (s0 + 0 < t) ? c[mi][ni][2 * h + 0] * C2 : -64.f;
                const float z1 = (s0 + 1 < t) ? c[mi][ni][2 * h + 1] * C2 : -64.f;
                __half2 e = h2exp2(__floats2half2_rn(z0, z1));
                const int kc = 2 * sb + (col >> 6);
                char* dst = (char*)g_St + (srow_base + kc) * 16384
                          + sw128((uint32_t)(row_local * 128 + (col & 63) * 2));
                *(uint32_t*)dst = *(uint32_t*)&e;
                float2 ef = __half22float2(e);
                rs[h] += ef.x + ef.y;
            }
        }
#pragma unroll
        for (int h = 0; h < 2; h++) {
            float v = rs[h];
            v += __shfl_xor_sync(0xFFFFFFFFu, v, 1);
            v += __shfl_xor_sync(0xFFFFFFFFu, v, 2);
            if (qid == 0) {
                const int row = warp_m * 32 + mi * 16 + quad + h * 8;
                atomicAdd(&rsum[row], v);
            }
        }
    }
    __syncthreads();
    if (tid < 64)
        atomicAdd(&g_den[b * T_ + tb6 * 64 + tid], rsum[tid]);
}

// ---------------------------------------------------------------------------
// Kernel 3: context = (S @ X) / den. CTA 128x128, 8 warps of 64x32, 3-stage
// bulk pipeline (2 bulk loads/iter). f16 MMA, f16 C store. Heavy-first.
// ---------------------------------------------------------------------------
__global__ __launch_bounds__(256) void k_av_mma() {
    const int nb = blockIdx.x;
    const int tb = (int)gridDim.y - 1 - (int)blockIdx.y;   // heavy-first
    const int b  = blockIdx.z;

    extern __shared__ __align__(1024) char smem[];
    __shared__ __align__(8) uint64_t bars[3];
    const uint32_t sbase = smem_u32(smem);
    const int tid = threadIdx.x, lane = tid & 31, wid = tid >> 5;
    const int warp_m = wid & 1, warp_n = wid >> 1;

    if (tid == 0) {
#pragma unroll
        for (int s = 0; s < 3; s++) MBAR_INIT(smem_u32(&bars[s]), 1);
    }
    __syncthreads();

    const char* SA = (const char*)g_St  + (size_t)((b * 16 + tb) * 32) * 16384;
    const char* XB = (const char*)g_XTt + (size_t)((b * 8 + nb) * 32) * 16384;

    float c[4][4][4];
#pragma unroll
    for (int mi = 0; mi < 4; mi++)
#pragma unroll
        for (int ni = 0; ni < 4; ni++)
#pragma unroll
            for (int k = 0; k < 4; k++) c[mi][ni][k] = 0.f;

    const int nIter = (tb + 1) * 2;
    if (tid == 0) {
#pragma unroll
        for (int s = 0; s < 2; s++) {
            if (s < nIter) {
                const uint32_t mb = smem_u32(&bars[s]);
                const uint32_t st = sbase + s * AV_STAGE;
                bar_expect(mb, AV_STAGE);
                bulk_ld(st,         SA + (size_t)s * 16384, 16384, mb);
                bulk_ld(st + 16384, XB + (size_t)s * 16384, 16384, mb);
            }
        }
    }

    const int rowsel = lane & 15;
    const int khalf  = (lane >> 4) * 16;

    for (int it = 0; it < nIter; ++it) {
        bar_wait(smem_u32(&bars[it % 3]), (uint32_t)((it / 3) & 1));
        __syncthreads();
        if (it + 2 < nIter && tid == 0) {
            const int ld = it + 2;
            const int s  = ld % 3;
            const uint32_t mb = smem_u32(&bars[s]);
            const uint32_t st = sbase + s * AV_STAGE;
            bar_expect(mb, AV_STAGE);
            bulk_ld(st,         SA + (size_t)ld * 16384, 16384, mb);
            bulk_ld(st + 16384, XB + (size_t)ld * 16384, 16384, mb);
        }
        const uint32_t sA = sbase + (it % 3) * AV_STAGE;
        const uint32_t sB = sA + 16384;
#pragma unroll
        for (int ks = 0; ks < 4; ks++) {
            const uint32_t kb = ks * 32 + khalf;
            uint32_t a[4][4];
#pragma unroll
            for (int mi = 0; mi < 4; mi++) {
                const uint32_t row = warp_m * 64 + mi * 16 + rowsel;
                ldmx4(a[mi][0], a[mi][1], a[mi][2], a[mi][3],
                      sA + row * 128 + (kb ^ ((row & 7) << 4)));
            }
            uint32_t bf[4][2];
#pragma unroll
            for (int nj = 0; nj < 2; nj++) {
                const uint32_t nrow = warp_n * 32 + nj * 16 + rowsel;
                uint32_t r0, r1, r2, r3;
                ldmx4(r0, r1, r2, r3, sB + nrow * 128 + (kb ^ ((nrow & 7) << 4)));
                bf[nj * 2 + 0][0] = r0; bf[nj * 2 + 1][0] = r1;
                bf[nj * 2 + 0][1] = r2; bf[nj * 2 + 1][1] = r3;
            }
#pragma unroll
            for (int mi = 0; mi < 4; mi++)
#pragma unroll
                for (int ni = 0; ni < 4; ni++)
                    mma_f16(c[mi][ni], a[mi], bf[ni][0], bf[ni][1]);
        }
    }

    // epilogue: divide by denom, f16 store (row-major g_Ch)
    const int quad = lane >> 2, qid = lane & 3;
#pragma unroll
    for (int mi = 0; mi < 4; mi++) {
#pragma unroll
        for (int h = 0; h < 2; h++) {
            const int row = warp_m * 64 + mi * 16 + quad + h * 8;
            const int t   = tb * 128 + row;
            const float den = g_den[b * T_ + t];
            const float inv = den > 0.f ? 1.f / den : 0.f;
            __half* crow = g_Ch + ((size_t)(b * T_ + t)) * D_ + nb * 128;
#pragma unroll
            for (int ni = 0; ni < 4; ni++) {
                const int col = warp_n * 32 + ni * 8 + qid * 2;
                __half2 hv = __floats2half2_rn(c[mi][ni][2 * h + 0] * inv,
                                               c[mi][ni][2 * h + 1] * inv);
                *(uint32_t*)(crow + col) = *(uint32_t*)&hv;
            }
        }
    }
}

// ---------------------------------------------------------------------------
// Kernel 4: cosine / novelty / gate / tanh-GELU (C in f16)
// ---------------------------------------------------------------------------
__global__ __launch_bounds__(256) void k_epi(const float* __restrict__ x,
                                             const float* __restrict__ p_la,
                                             const float* __restrict__ p_ls,
                                             float* __restrict__ out) {
    const int row = blockIdx.x;
    const int tid = threadIdx.x;
    const float4 xv = *((const float4*)x + (size_t)row * 256 + tid);
    const uint2 cu  = *((const uint2*)g_Ch + (size_t)row * 256 + tid);
    float2 c01 = __half22float2(*(const __half2*)&cu.x);
    float2 c23 = __half22float2(*(const __half2*)&cu.y);

    float xx = xv.x * xv.x + xv.y * xv.y + xv.z * xv.z + xv.w * xv.w;
    float cc = c01.x * c01.x + c01.y * c01.y + c23.x * c23.x + c23.y * c23.y;
    float xc = xv.x * c01.x + xv.y * c01.y + xv.z * c23.x + xv.w * c23.y;

#pragma unroll
    for (int o = 16; o; o >>= 1) {
        xx += __shfl_down_sync(0xFFFFFFFFu, xx, o);
        cc += __shfl_down_sync(0xFFFFFFFFu, cc, o);
        xc += __shfl_down_sync(0xFFFFFFFFu, xc, o);
    }

    __shared__ float s_xx[8], s_cc[8], s_xc[8];
    __shared__ float s_gate;
    const int lane = tid & 31, w = tid >> 5;
    if (lane == 0) { s_xx[w] = xx; s_cc[w] = cc; s_xc[w] = xc; }
    __syncthreads();
    if (tid == 0) {
        float fxx = 0.f, fcc = 0.f, fxc = 0.f;
#pragma unroll
        for (int k = 0; k < 8; k++) { fxx += s_xx[k]; fcc += s_cc[k]; fxc += s_xc[k]; }
        const float nx = fmaxf(sqrtf(fxx), 1e-12f);
        const float nc = fmaxf(sqrtf(fcc), 1e-12f);
        const float cosv = fxc / (nx * nc);
        const float nov  = fminf(fmaxf(1.f - cosv, 0.f), 2.f) * 0.5f;
        const float alpha = softplusf_(*p_la);
        const float sigma = softplusf_(*p_ls);
        s_gate = 1.f + alpha * tanhf(sigma * nov);
    }
    __syncthreads();
    const float g = s_gate;

    float4 o;
    o.x = gelu_tanh_(xv.x * g);
    o.y = gelu_tanh_(xv.y * g);
    o.z = gelu_tanh_(xv.z * g);
    o.w = gelu_tanh_(xv.w * g);
    *((float4*)out + (size_t)row * 256 + tid) = o;
}

// ---------------------------------------------------------------------------
extern "C" void kernel_launch(void* const* d_in, const int* in_sizes, int n_in,
                              void* d_out, int out_size) {
    const float* x  = (const float*)d_in[0];
    const float* la = (const float*)d_in[1];
    const float* ls = (const float*)d_in[2];
    float* out = (float*)d_out;

    const int qk_smem = 3 * QK_STAGE;   // 73728
    const int av_smem = 3 * AV_STAGE;   // 98304
    cudaFuncSetAttribute(k_qk_mma, cudaFuncAttributeMaxDynamicSharedMemorySize, qk_smem);
    cudaFuncSetAttribute(k_av_mma, cudaFuncAttributeMaxDynamicSharedMemorySize, av_smem);

    k_zero<<<(B_ * T_ + 1023) / 1024, 1024>>>();

    dim3 gc(T_ / 32, D_ / 32, B_);
    k_cvt<<<gc, dim3(16, 16)>>>(x);

    dim3 g1(16, 32, B_);
    k_qk_mma<<<g1, 256, qk_smem>>>();

    dim3 g3(8, 16, B_);
    k_av_mma<<<g3, 256, av_smem>>>();

    k_epi<<<B_ * T_, 256>>>(x, la, ls, out);
}

// round 15
// speedup vs baseline: 1.7075x; 1.0805x over previous
#include <cuda_runtime.h>
#include <cuda_bf16.h>
#include <cuda_fp16.h>
#include <stdint.h>

#define B_ 8
#define T_ 2048
#define D_ 1024
#define SCALE_ 0.03125f   // 1/sqrt(1024)

// k_qk: stage = A tile 8KB + B tiles 16KB
#define QK_STAGE 24576
// k_av: stage = S half-tile 8KB + XT tile 16KB
#define AV_STAGE 24576

// ---------------------------------------------------------------------------
// Scratch — tiled, pre-swizzled layouts
//   g_Xh : bf16 X tiles  [b][t64:32][kc:16] of 64r x 64c (8KB each)
//   g_St : f16  S tiles  [b][tb:16][kc:32]  of 128r x 64c (16KB each)
//   g_XTt: f16  XT tiles [b][nb:8][kc:32]   of 128r(d) x 64c(t) (16KB each)
// ---------------------------------------------------------------------------
__device__ __nv_bfloat16 g_Xh [(size_t)B_ * 32 * 16 * 4096];
__device__ __half        g_St [(size_t)B_ * 16 * 32 * 8192];
__device__ __half        g_XTt[(size_t)B_ * 8  * 32 * 8192];
__device__ __half        g_Ch [(size_t)B_ * T_ * D_];     // context f16 (row-major)
__device__ float         g_den[B_ * T_];

// ---------------------------------------------------------------------------
// Helpers
// ---------------------------------------------------------------------------
__device__ __forceinline__ uint32_t smem_u32(const void* p) {
    uint32_t a;
    asm("{ .reg .u64 t; cvta.to.shared.u64 t, %1; cvt.u32.u64 %0, t; }"
        : "=r"(a) : "l"(p));
    return a;
}

#define MBAR_INIT(addr, cnt) \
    asm volatile("mbarrier.init.shared.b64 [%0], %1;" :: "r"(addr), "r"(cnt) : "memory")

__device__ __forceinline__ void bar_expect(uint32_t mbar, uint32_t bytes) {
    asm volatile("mbarrier.arrive.expect_tx.shared.b64 _, [%0], %1;"
                 :: "r"(mbar), "r"(bytes) : "memory");
}

__device__ __forceinline__ void bar_wait(uint32_t mbar, uint32_t phase) {
    asm volatile(
        "{\n\t.reg .pred P;\n"
        "W%=:\n\t"
        "mbarrier.try_wait.parity.shared.b64 P, [%0], %1;\n\t"
        "@!P bra W%=;\n\t}"
        :: "r"(mbar), "r"(phase) : "memory");
}

__device__ __forceinline__ void bulk_ld(uint32_t dst, const void* src,
                                        uint32_t bytes, uint32_t mbar) {
    asm volatile(
        "cp.async.bulk.shared::cluster.global.mbarrier::complete_tx::bytes "
        "[%0], [%1], %2, [%3];"
        :: "r"(dst), "l"(src), "r"(bytes), "r"(mbar) : "memory");
}

__device__ __forceinline__ void ldmx4(uint32_t& r0, uint32_t& r1,
                                      uint32_t& r2, uint32_t& r3, uint32_t addr) {
    asm volatile("ldmatrix.sync.aligned.m8n8.x4.shared.b16 {%0,%1,%2,%3}, [%4];"
                 : "=r"(r0), "=r"(r1), "=r"(r2), "=r"(r3) : "r"(addr));
}

__device__ __forceinline__ void mma_bf16(float* c, const uint32_t* a,
                                         uint32_t b0, uint32_t b1) {
    asm volatile(
        "mma.sync.aligned.m16n8k16.row.col.f32.bf16.bf16.f32 "
        "{%0,%1,%2,%3}, {%4,%5,%6,%7}, {%8,%9}, {%0,%1,%2,%3};"
        : "+f"(c[0]), "+f"(c[1]), "+f"(c[2]), "+f"(c[3])
        : "r"(a[0]), "r"(a[1]), "r"(a[2]), "r"(a[3]), "r"(b0), "r"(b1));
}

__device__ __forceinline__ void mma_f16(float* c, const uint32_t* a,
                                        uint32_t b0, uint32_t b1) {
    asm volatile(
        "mma.sync.aligned.m16n8k16.row.col.f32.f16.f16.f32 "
        "{%0,%1,%2,%3}, {%4,%5,%6,%7}, {%8,%9}, {%0,%1,%2,%3};"
        : "+f"(c[0]), "+f"(c[1]), "+f"(c[2]), "+f"(c[3])
        : "r"(a[0]), "r"(a[1]), "r"(a[2]), "r"(a[3]), "r"(b0), "r"(b1));
}

__device__ __forceinline__ uint32_t sw128(uint32_t off) {
    return off ^ ((off >> 3) & 0x70);
}

__device__ __forceinline__ float softplusf_(float v) {
    return v > 20.f ? v : log1pf(__expf(v));
}
__device__ __forceinline__ float gelu_tanh_(float v) {
    float u = 0.7978845608028654f * (v + 0.044715f * v * v * v);
    return 0.5f * v * (1.f + tanhf(u));
}

// ---------------------------------------------------------------------------
// Kernel Z: zero denominators
// ---------------------------------------------------------------------------
__global__ void k_zero() {
    const int i = blockIdx.x * 1024 + threadIdx.x;
    if (i < B_ * T_) g_den[i] = 0.f;
}

// ---------------------------------------------------------------------------
// Kernel 0: convert x -> tiled bf16 X tiles + tiled f16 XT tiles
// ---------------------------------------------------------------------------
__global__ __launch_bounds__(256) void k_cvt(const float* __restrict__ x) {
    __shared__ float tile[32][33];
    const int b  = blockIdx.z;
    const int t0 = blockIdx.x * 32;
    const int d0 = blockIdx.y * 32;
    const int lx = threadIdx.x;
    const int ly = threadIdx.y;
    const float* X = x + (size_t)b * T_ * D_;

#pragma unroll
    for (int r = 0; r < 2; r++) {
        const int t = t0 + ly + r * 16;
        const int d = d0 + lx * 2;
        float2 v = *(const float2*)(X + (size_t)t * D_ + d);
        __nv_bfloat162 h = __floats2bfloat162_rn(v.x, v.y);
        const size_t tile_idx = (size_t)((b * 32 + (t >> 6)) * 16 + (d >> 6));
        char* dst = (char*)g_Xh + tile_idx * 8192
                  + sw128((uint32_t)((t & 63) * 128 + (d & 63) * 2));
        *(uint32_t*)dst = *(uint32_t*)&h;
        tile[ly + r * 16][lx * 2 + 0] = v.x;
        tile[ly + r * 16][lx * 2 + 1] = v.y;
    }
    __syncthreads();
#pragma unroll
    for (int r = 0; r < 2; r++) {
        const int d  = d0 + ly + r * 16;
        const int tp = t0 + lx * 2;
        __half2 h = __floats2half2_rn(tile[lx * 2 + 0][ly + r * 16],
                                      tile[lx * 2 + 1][ly + r * 16]);
        const size_t tile_idx = (size_t)((b * 8 + (d >> 7)) * 32 + (tp >> 6));
        char* dst = (char*)g_XTt + tile_idx * 16384
                  + sw128((uint32_t)((d & 127) * 128 + (tp & 63) * 2));
        *(uint32_t*)dst = *(uint32_t*)&h;
    }
}

// ---------------------------------------------------------------------------
// MMA cores: CTA 64(m) x 128(n), 8 warps 2m x 4n of 32x32
// A tile: 64 rows x 128B contiguous. B tile: 128 rows x 128B contiguous.
// ---------------------------------------------------------------------------
__device__ __forceinline__ void mma_chunk_qk(uint32_t sA, uint32_t sB,
                                             int warp_m, int warp_n, int lane,
                                             float c[2][4][4]) {
    const int rowsel = lane & 15;
    const int khalf  = (lane >> 4) * 16;
    const uint32_t a0 = sA + (warp_m * 32 + 0  + rowsel) * 128;
    const uint32_t a1 = sA + (warp_m * 32 + 16 + rowsel) * 128;
    const uint32_t b0a = sB + (warp_n * 32 + 0  + rowsel) * 128;
    const uint32_t b1a = sB + (warp_n * 32 + 16 + rowsel) * 128;
    const uint32_t xa0 = ((warp_m * 32 + 0  + rowsel) & 7) << 4;
    const uint32_t xa1 = ((warp_m * 32 + 16 + rowsel) & 7) << 4;
    const uint32_t xb0 = ((warp_n * 32 + 0  + rowsel) & 7) << 4;
    const uint32_t xb1 = ((warp_n * 32 + 16 + rowsel) & 7) << 4;
#pragma unroll
    for (int ks = 0; ks < 4; ks++) {
        const uint32_t kb = ks * 32 + khalf;
        uint32_t a[2][4];
        ldmx4(a[0][0], a[0][1], a[0][2], a[0][3], a0 + (kb ^ xa0));
        ldmx4(a[1][0], a[1][1], a[1][2], a[1][3], a1 + (kb ^ xa1));
        uint32_t b[4][2];
        {
            uint32_t r0, r1, r2, r3;
            ldmx4(r0, r1, r2, r3, b0a + (kb ^ xb0));
            b[0][0] = r0; b[1][0] = r1; b[0][1] = r2; b[1][1] = r3;
            ldmx4(r0, r1, r2, r3, b1a + (kb ^ xb1));
            b[2][0] = r0; b[3][0] = r1; b[2][1] = r2; b[3][1] = r3;
        }
#pragma unroll
        for (int mi = 0; mi < 2; mi++)
#pragma unroll
            for (int ni = 0; ni < 4; ni++)
                mma_bf16(c[mi][ni], a[mi], b[ni][0], b[ni][1]);
    }
}

__device__ __forceinline__ void mma_chunk_av(uint32_t sA, uint32_t sB,
                                             int warp_m, int warp_n, int lane,
                                             float c[2][4][4]) {
    const int rowsel = lane & 15;
    const int khalf  = (lane >> 4) * 16;
    const uint32_t a0 = sA + (warp_m * 32 + 0  + rowsel) * 128;
    const uint32_t a1 = sA + (warp_m * 32 + 16 + rowsel) * 128;
    const uint32_t b0a = sB + (warp_n * 32 + 0  + rowsel) * 128;
    const uint32_t b1a = sB + (warp_n * 32 + 16 + rowsel) * 128;
    const uint32_t xa0 = ((warp_m * 32 + 0  + rowsel) & 7) << 4;
    const uint32_t xa1 = ((warp_m * 32 + 16 + rowsel) & 7) << 4;
    const uint32_t xb0 = ((warp_n * 32 + 0  + rowsel) & 7) << 4;
    const uint32_t xb1 = ((warp_n * 32 + 16 + rowsel) & 7) << 4;
#pragma unroll
    for (int ks = 0; ks < 4; ks++) {
        const uint32_t kb = ks * 32 + khalf;
        uint32_t a[2][4];
        ldmx4(a[0][0], a[0][1], a[0][2], a[0][3], a0 + (kb ^ xa0));
        ldmx4(a[1][0], a[1][1], a[1][2], a[1][3], a1 + (kb ^ xa1));
        uint32_t b[4][2];
        {
            uint32_t r0, r1, r2, r3;
            ldmx4(r0, r1, r2, r3, b0a + (kb ^ xb0));
            b[0][0] = r0; b[1][0] = r1; b[0][1] = r2; b[1][1] = r3;
            ldmx4(r0, r1, r2, r3, b1a + (kb ^ xb1));
            b[2][0] = r0; b[3][0] = r1; b[2][1] = r2; b[3][1] = r3;
        }
#pragma unroll
        for (int mi = 0; mi < 2; mi++)
#pragma unroll
            for (int ni = 0; ni < 4; ni++)
                mma_f16(c[mi][ni], a[mi], b[ni][0], b[ni][1]);
    }
}

// ---------------------------------------------------------------------------
// Kernel 1: S = exp(SCALE * X X^T) f16 tiled, strict causal, fused row-sum.
// Bulk-copy pipeline: 3 bulk loads/iter. (unchanged from R14)
// ---------------------------------------------------------------------------
__global__ __launch_bounds__(256, 3) void k_qk_mma() {
    const int sb  = blockIdx.x;
    const int tb6 = blockIdx.y;
    const int b   = blockIdx.z;
    if (sb > (tb6 >> 1)) return;

    extern __shared__ __align__(1024) char smem[];
    __shared__ __align__(8) uint64_t bars[3];
    __shared__ float rsum[64];
    const uint32_t sbase = smem_u32(smem);
    const int tid = threadIdx.x, lane = tid & 31, wid = tid >> 5;
    const int warp_m = wid & 1, warp_n = wid >> 1;

    if (tid < 64) rsum[tid] = 0.f;
    if (tid == 0) {
#pragma unroll
        for (int s = 0; s < 3; s++) MBAR_INIT(smem_u32(&bars[s]), 1);
    }
    __syncthreads();

    const char* XA  = (const char*)g_Xh + (size_t)((b * 32 + tb6) * 16) * 8192;
    const char* XB0 = (const char*)g_Xh + (size_t)((b * 32 + 2 * sb) * 16) * 8192;
    const char* XB1 = (const char*)g_Xh + (size_t)((b * 32 + 2 * sb + 1) * 16) * 8192;

    float c[2][4][4];
#pragma unroll
    for (int mi = 0; mi < 2; mi++)
#pragma unroll
        for (int ni = 0; ni < 4; ni++)
#pragma unroll
            for (int k = 0; k < 4; k++) c[mi][ni][k] = 0.f;

    const int nIter = 16;
    if (tid == 0) {
#pragma unroll
        for (int s = 0; s < 2; s++) {
            const uint32_t mb = smem_u32(&bars[s]);
            const uint32_t st = sbase + s * QK_STAGE;
            bar_expect(mb, QK_STAGE);
            bulk_ld(st,         XA  + (size_t)s * 8192, 8192, mb);
            bulk_ld(st + 8192,  XB0 + (size_t)s * 8192, 8192, mb);
            bulk_ld(st + 16384, XB1 + (size_t)s * 8192, 8192, mb);
        }
    }

    for (int it = 0; it < nIter; ++it) {
        bar_wait(smem_u32(&bars[it % 3]), (uint32_t)((it / 3) & 1));
        __syncthreads();
        if (it + 2 < nIter && tid == 0) {
            const int ld = it + 2;
            const int s  = ld % 3;
            const uint32_t mb = smem_u32(&bars[s]);
            const uint32_t st = sbase + s * QK_STAGE;
            bar_expect(mb, QK_STAGE);
            bulk_ld(st,         XA  + (size_t)ld * 8192, 8192, mb);
            bulk_ld(st + 8192,  XB0 + (size_t)ld * 8192, 8192, mb);
            bulk_ld(st + 16384, XB1 + (size_t)ld * 8192, 8192, mb);
        }
        const uint32_t st = sbase + (it % 3) * QK_STAGE;
        mma_chunk_qk(st, st + 8192, warp_m, warp_n, lane, c);
    }

    const int quad = lane >> 2, qid = lane & 3;
    const float C2 = 0.045084219f;   // SCALE * log2(e)
    const size_t srow_base = (size_t)((b * 16 + (tb6 >> 1)) * 32);
#pragma unroll
    for (int mi = 0; mi < 2; mi++) {
        float rs[2] = {0.f, 0.f};
#pragma unroll
        for (int h = 0; h < 2; h++) {
            const int row = warp_m * 32 + mi * 16 + quad + h * 8;
            const int t   = tb6 * 64 + row;
            const int row_local = (tb6 & 1) * 64 + row;
#pragma unroll
            for (int ni = 0; ni < 4; ni++) {
                const int col = warp_n * 32 + ni * 8 + qid * 2;
                const int s0  = sb * 128 + col;
                const float z0 = (s0 + 0 < t) ? c[mi][ni][2 * h + 0] * C2 : -64.f;
                const float z1 = (s0 + 1 < t) ? c[mi][ni][2 * h + 1] * C2 : -64.f;
                __half2 e = h2exp2(__floats2half2_rn(z0, z1));
                const int kc = 2 * sb + (col >> 6);
                char* dst = (char*)g_St + (srow_base + kc) * 16384
                          + sw128((uint32_t)(row_local * 128 + (col & 63) * 2));
                *(uint32_t*)dst = *(uint32_t*)&e;
                float2 ef = __half22float2(e);
                rs[h] += ef.x + ef.y;
            }
        }
#pragma unroll
        for (int h = 0; h < 2; h++) {
            float v = rs[h];
            v += __shfl_xor_sync(0xFFFFFFFFu, v, 1);
            v += __shfl_xor_sync(0xFFFFFFFFu, v, 2);
            if (qid == 0) {
                const int row = warp_m * 32 + mi * 16 + quad + h * 8;
                atomicAdd(&rsum[row], v);
            }
        }
    }
    __syncthreads();
    if (tid < 64)
        atomicAdd(&g_den[b * T_ + tb6 * 64 + tid], rsum[tid]);
}

// ---------------------------------------------------------------------------
// Kernel 3: context = (S @ X) / den. NEW SHAPE: CTA 64(t) x 128(d),
// 8 warps 2m x 4n of 32x32, 24KB stages, 3 CTA/SM (mirror of k_qk).
// A = 8KB S half-tile slice (contiguous), B = 16KB XT tile. Heavy-first.
// ---------------------------------------------------------------------------
__global__ __launch_bounds__(256, 3) void k_av_mma() {
    const int nb  = blockIdx.x;                 // 0..7
    const int tb6 = 31 - (int)blockIdx.y;       // heavy-first, 0..31
    const int b   = blockIdx.z;

    extern __shared__ __align__(1024) char smem[];
    __shared__ __align__(8) uint64_t bars[3];
    const uint32_t sbase = smem_u32(smem);
    const int tid = threadIdx.x, lane = tid & 31, wid = tid >> 5;
    const int warp_m = wid & 1, warp_n = wid >> 1;

    if (tid == 0) {
#pragma unroll
        for (int s = 0; s < 3; s++) MBAR_INIT(smem_u32(&bars[s]), 1);
    }
    __syncthreads();

    // S rows tb6*64 .. +63 = half-tile slice of S tile (b, tb6>>1, kc)
    const char* SA = (const char*)g_St
                   + (size_t)((b * 16 + (tb6 >> 1)) * 32) * 16384
                   + (size_t)(tb6 & 1) * 8192;
    const char* XB = (const char*)g_XTt + (size_t)((b * 8 + nb) * 32) * 16384;

    float c[2][4][4];
#pragma unroll
    for (int mi = 0; mi < 2; mi++)
#pragma unroll
        for (int ni = 0; ni < 4; ni++)
#pragma unroll
            for (int k = 0; k < 4; k++) c[mi][ni][k] = 0.f;

    const int nIter = ((tb6 >> 1) + 1) * 2;
    if (tid == 0) {
#pragma unroll
        for (int s = 0; s < 2; s++) {
            if (s < nIter) {
                const uint32_t mb = smem_u32(&bars[s]);
                const uint32_t st = sbase + s * AV_STAGE;
                bar_expect(mb, AV_STAGE);
                bulk_ld(st,        SA + (size_t)s * 16384, 8192,  mb);
                bulk_ld(st + 8192, XB + (size_t)s * 16384, 16384, mb);
            }
        }
    }

    for (int it = 0; it < nIter; ++it) {
        bar_wait(smem_u32(&bars[it % 3]), (uint32_t)((it / 3) & 1));
        __syncthreads();
        if (it + 2 < nIter && tid == 0) {
            const int ld = it + 2;
            const int s  = ld % 3;
            const uint32_t mb = smem_u32(&bars[s]);
            const uint32_t st = sbase + s * AV_STAGE;
            bar_expect(mb, AV_STAGE);
            bulk_ld(st,        SA + (size_t)ld * 16384, 8192,  mb);
            bulk_ld(st + 8192, XB + (size_t)ld * 16384, 16384, mb);
        }
        const uint32_t st = sbase + (it % 3) * AV_STAGE;
        mma_chunk_av(st, st + 8192, warp_m, warp_n, lane, c);
    }

    // epilogue: divide by denom, f16 store (row-major g_Ch)
    const int quad = lane >> 2, qid = lane & 3;
#pragma unroll
    for (int mi = 0; mi < 2; mi++) {
#pragma unroll
        for (int h = 0; h < 2; h++) {
            const int row = warp_m * 32 + mi * 16 + quad + h * 8;
            const int t   = tb6 * 64 + row;
            const float den = g_den[b * T_ + t];
            const float inv = den > 0.f ? 1.f / den : 0.f;
            __half* crow = g_Ch + ((size_t)(b * T_ + t)) * D_ + nb * 128;
#pragma unroll
            for (int ni = 0; ni < 4; ni++) {
                const int col = warp_n * 32 + ni * 8 + qid * 2;
                __half2 hv = __floats2half2_rn(c[mi][ni][2 * h + 0] * inv,
                                               c[mi][ni][2 * h + 1] * inv);
                *(uint32_t*)(crow + col) = *(uint32_t*)&hv;
            }
        }
    }
}

// ---------------------------------------------------------------------------
// Kernel 4: cosine / novelty / gate / tanh-GELU (C in f16)
// ---------------------------------------------------------------------------
__global__ __launch_bounds__(256) void k_epi(const float* __restrict__ x,
                                             const float* __restrict__ p_la,
                                             const float* __restrict__ p_ls,
                                             float* __restrict__ out) {
    const int row = blockIdx.x;
    const int tid = threadIdx.x;
    const float4 xv = *((const float4*)x + (size_t)row * 256 + tid);
    const uint2 cu  = *((const uint2*)g_Ch + (size_t)row * 256 + tid);
    float2 c01 = __half22float2(*(const __half2*)&cu.x);
    float2 c23 = __half22float2(*(const __half2*)&cu.y);

    float xx = xv.x * xv.x + xv.y * xv.y + xv.z * xv.z + xv.w * xv.w;
    float cc = c01.x * c01.x + c01.y * c01.y + c23.x * c23.x + c23.y * c23.y;
    float xc = xv.x * c01.x + xv.y * c01.y + xv.z * c23.x + xv.w * c23.y;

#pragma unroll
    for (int o = 16; o; o >>= 1) {
        xx += __shfl_down_sync(0xFFFFFFFFu, xx, o);
        cc += __shfl_down_sync(0xFFFFFFFFu, cc, o);
        xc += __shfl_down_sync(0xFFFFFFFFu, xc, o);
    }

    __shared__ float s_xx[8], s_cc[8], s_xc[8];
    __shared__ float s_gate;
    const int lane = tid & 31, w = tid >> 5;
    if (lane == 0) { s_xx[w] = xx; s_cc[w] = cc; s_xc[w] = xc; }
    __syncthreads();
    if (tid == 0) {
        float fxx = 0.f, fcc = 0.f, fxc = 0.f;
#pragma unroll
        for (int k = 0; k < 8; k++) { fxx += s_xx[k]; fcc += s_cc[k]; fxc += s_xc[k]; }
        const float nx = fmaxf(sqrtf(fxx), 1e-12f);
        const float nc = fmaxf(sqrtf(fcc), 1e-12f);
        const float cosv = fxc / (nx * nc);
        const float nov  = fminf(fmaxf(1.f - cosv, 0.f), 2.f) * 0.5f;
        const float alpha = softplusf_(*p_la);
        const float sigma = softplusf_(*p_ls);
        s_gate = 1.f + alpha * tanhf(sigma * nov);
    }
    __syncthreads();
    const float g = s_gate;

    float4 o;
    o.x = gelu_tanh_(xv.x * g);
    o.y = gelu_tanh_(xv.y * g);
    o.z = gelu_tanh_(xv.z * g);
    o.w = gelu_tanh_(xv.w * g);
    *((float4*)out + (size_t)row * 256 + tid) = o;
}

// ---------------------------------------------------------------------------
extern "C" void kernel_launch(void* const* d_in, const int* in_sizes, int n_in,
                              void* d_out, int out_size) {
    const float* x  = (const float*)d_in[0];
    const float* la = (const float*)d_in[1];
    const float* ls = (const float*)d_in[2];
    float* out = (float*)d_out;

    const int qk_smem = 3 * QK_STAGE;   // 73728
    const int av_smem = 3 * AV_STAGE;   // 73728
    cudaFuncSetAttribute(k_qk_mma, cudaFuncAttributeMaxDynamicSharedMemorySize, qk_smem);
    cudaFuncSetAttribute(k_av_mma, cudaFuncAttributeMaxDynamicSharedMemorySize, av_smem);

    k_zero<<<(B_ * T_ + 1023) / 1024, 1024>>>();

    dim3 gc(T_ / 32, D_ / 32, B_);
    k_cvt<<<gc, dim3(16, 16)>>>(x);

    dim3 g1(16, 32, B_);
    k_qk_mma<<<g1, 256, qk_smem>>>();

    dim3 g3(8, 32, B_);
    k_av_mma<<<g3, 256, av_smem>>>();

    k_epi<<<B_ * T_, 256>>>(x, la, ls, out);
}